// round 12
// baseline (speedup 1.0000x reference)
#include <cuda_runtime.h>
#include <cuda_bf16.h>
#include <math.h>
#include <math_constants.h>
#include <stdint.h>

// Problem constants
#define TT   2048
#define HID  2048
#define NH   16
#define NKV  8
#define DH   128
#define QKVW ((NH + 2 * NKV) * DH)   // 4096
#define QW   (NH * DH)               // 2048
#define KVW  (NKV * DH)              // 1024
#define EPS  1e-6f

// Scratch (allocation-free rule: __device__ globals)
__device__ __nv_bfloat16 g_ah[(size_t)TT * HID];     // GEMM A hi / attn-out hi
__device__ __nv_bfloat16 g_al[(size_t)TT * HID];     // GEMM A lo / attn-out lo
__device__ __nv_bfloat16 g_bh[(size_t)QKVW * HID];   // B^T hi ([N,K])
__device__ __nv_bfloat16 g_bl[(size_t)QKVW * HID];   // B^T lo
__device__ __nv_bfloat16 g_qsh[(size_t)TT * QW],  g_qsl[(size_t)TT * QW];   // split Q (scaled)
__device__ __nv_bfloat16 g_ksh[(size_t)TT * KVW], g_ksl[(size_t)TT * KVW];  // split K
__device__ __nv_bfloat16 g_vsh[(size_t)TT * KVW], g_vsl[(size_t)TT * KVW];  // split V
__device__ float2 g_rope[(size_t)TT * 64];           // (cos, sin) per (t, d)

// ---------------------------------------------------------------------------
// PTX helpers (base sm_103 target — HMMA mma.sync + ldmatrix + cp.async)
// ---------------------------------------------------------------------------
__device__ __forceinline__ void mma16816(float d[4],
                                         uint32_t a0, uint32_t a1, uint32_t a2, uint32_t a3,
                                         uint32_t b0, uint32_t b1)
{
    asm volatile(
        "mma.sync.aligned.m16n8k16.row.col.f32.bf16.bf16.f32 "
        "{%0,%1,%2,%3}, {%4,%5,%6,%7}, {%8,%9}, {%0,%1,%2,%3};\n"
        : "+f"(d[0]), "+f"(d[1]), "+f"(d[2]), "+f"(d[3])
        : "r"(a0), "r"(a1), "r"(a2), "r"(a3), "r"(b0), "r"(b1));
}

__device__ __forceinline__ void ldsm_x4(uint32_t& r0, uint32_t& r1,
                                        uint32_t& r2, uint32_t& r3, uint32_t addr)
{
    asm volatile("ldmatrix.sync.aligned.m8n8.x4.shared.b16 {%0,%1,%2,%3}, [%4];"
                 : "=r"(r0), "=r"(r1), "=r"(r2), "=r"(r3) : "r"(addr));
}

__device__ __forceinline__ void ldsm_x4_t(uint32_t& r0, uint32_t& r1,
                                          uint32_t& r2, uint32_t& r3, uint32_t addr)
{
    asm volatile("ldmatrix.sync.aligned.m8n8.x4.trans.shared.b16 {%0,%1,%2,%3}, [%4];"
                 : "=r"(r0), "=r"(r1), "=r"(r2), "=r"(r3) : "r"(addr));
}

__device__ __forceinline__ uint32_t su32(const void* p) {
    return (uint32_t)__cvta_generic_to_shared(p);
}

__device__ __forceinline__ uint32_t pack_bf16x2(float a, float b) {
    __nv_bfloat162 t = __floats2bfloat162_rn(a, b);
    return *(uint32_t*)&t;
}

__device__ __forceinline__ void cp_async16(uint32_t dst, const void* src) {
    asm volatile("cp.async.cg.shared.global [%0], [%1], 16;" :: "r"(dst), "l"(src));
}
__device__ __forceinline__ void cp_commit() {
    asm volatile("cp.async.commit_group;" ::: "memory");
}
template <int N>
__device__ __forceinline__ void cp_wait() {
    asm volatile("cp.async.wait_group %0;" :: "n"(N) : "memory");
}

// hi/lo split of a float4, stored as 2x bf162 each
__device__ __forceinline__ void split4_store(float4 v, __nv_bfloat16* hp, __nv_bfloat16* lp) {
    __nv_bfloat16 h0 = __float2bfloat16(v.x), h1 = __float2bfloat16(v.y);
    __nv_bfloat16 h2 = __float2bfloat16(v.z), h3 = __float2bfloat16(v.w);
    *(uint32_t*)(hp)     = pack_bf16x2(__bfloat162float(h0), __bfloat162float(h1));
    *(uint32_t*)(hp + 2) = pack_bf16x2(__bfloat162float(h2), __bfloat162float(h3));
    *(uint32_t*)(lp)     = pack_bf16x2(v.x - __bfloat162float(h0), v.y - __bfloat162float(h1));
    *(uint32_t*)(lp + 2) = pack_bf16x2(v.z - __bfloat162float(h2), v.w - __bfloat162float(h3));
}

// hi/lo split of 2 floats -> two u32 stores
__device__ __forceinline__ void split2_store(float a, float b,
                                             __nv_bfloat16* hp, __nv_bfloat16* lp) {
    float ha = __bfloat162float(__float2bfloat16(a));
    float hb = __bfloat162float(__float2bfloat16(b));
    *(uint32_t*)hp = pack_bf16x2(ha, hb);
    *(uint32_t*)lp = pack_bf16x2(a - ha, b - hb);
}

// ---------------------------------------------------------------------------
// Split conversion (+ RoPE table build by the first TT*64 threads).
// ---------------------------------------------------------------------------
__global__ __launch_bounds__(256) void split_kernel(
    const float* __restrict__ x,
    __nv_bfloat16* __restrict__ hi, __nv_bfloat16* __restrict__ lo, int n,
    const int* __restrict__ positions, float2* __restrict__ rope)
{
    int j = blockIdx.x * blockDim.x + threadIdx.x;
    if (rope && j < TT * 64) {
        int t = j >> 6;
        int d = j & 63;
        float pos = (float)positions[t];
        float inv_freq = powf(10000.f, -(float)d * (1.f / 64.f));
        float sv, cv;
        sincosf(pos * inv_freq, &sv, &cv);
        rope[j] = make_float2(cv, sv);
    }
    int i = j * 4;
    if (i >= n) return;
    float4 v = *(const float4*)(x + i);
    split4_store(v, hi + i, lo + i);
}

// ---------------------------------------------------------------------------
// Transpose + split: W[K,N] fp32 -> Th/Tl [N,K] bf16. K,N % 32 == 0.
// ---------------------------------------------------------------------------
__global__ __launch_bounds__(256) void transpose_split_kernel(
    const float* __restrict__ W,
    __nv_bfloat16* __restrict__ Th, __nv_bfloat16* __restrict__ Tl,
    int K, int N)
{
    __shared__ float tile[32][33];
    const int bn = blockIdx.x * 32;
    const int bk = blockIdx.y * 32;
    const int tx = threadIdx.x;
    const int ty = threadIdx.y;
#pragma unroll
    for (int j = 0; j < 32; j += 8)
        tile[ty + j][tx] = W[(size_t)(bk + ty + j) * N + bn + tx];
    __syncthreads();
#pragma unroll
    for (int j = 0; j < 32; j += 8) {
        float v = tile[tx][ty + j];
        __nv_bfloat16 h = __float2bfloat16(v);
        __nv_bfloat16 l = __float2bfloat16(v - __bfloat162float(h));
        size_t o = (size_t)(bn + ty + j) * K + bk + tx;
        Th[o] = h;
        Tl[o] = l;
    }
}

// ---------------------------------------------------------------------------
// mma.sync bf16x3 GEMM: cp.async double-buffered (single barrier per chunk),
// ldmatrix frags, dynamic smem 80 KB, 2 CTAs/SM.
// FUSED=true: QKV projection with RMSNorm+RoPE(table)+split epilogue.
// ---------------------------------------------------------------------------
#define GST   10240   // bytes per stage per array (128 rows x 80B)
#define GARR  20480   // bytes per array (2 stages)
#define GEMM_SMEM 81920

template<bool FUSED>
__global__ __launch_bounds__(256, 2) void gemm_mma_kernel_t(
    int M, int N, int K,
    const __nv_bfloat16* __restrict__ Ah, const __nv_bfloat16* __restrict__ Al,
    const __nv_bfloat16* __restrict__ Bh, const __nv_bfloat16* __restrict__ Bl,
    float* __restrict__ C,
    const float2* __restrict__ rope,
    const float* __restrict__ qw, const float* __restrict__ kw,
    __nv_bfloat16* __restrict__ qsh, __nv_bfloat16* __restrict__ qsl,
    __nv_bfloat16* __restrict__ ksh, __nv_bfloat16* __restrict__ ksl,
    __nv_bfloat16* __restrict__ vsh, __nv_bfloat16* __restrict__ vsl)
{
    extern __shared__ __align__(16) char blob[];

    const int tid  = threadIdx.x;
    const int lane = tid & 31;
    const int wid  = tid >> 5;
    const int wm   = wid >> 2;
    const int wn   = wid & 3;
    const int gq   = lane >> 2;
    const int tg   = lane & 3;
    const int bm = blockIdx.y * 128;
    const int bn = blockIdx.x * 128;

    const uint32_t ub = su32(blob);
    const uint32_t a_off = (uint32_t)((lane & 15) * 80 + (lane & 16));
    const uint32_t b_off = (uint32_t)(((lane & 7) + ((lane >> 4) << 3)) * 80 + (((lane >> 3) & 1) << 4));

    float acc[4][4][4];
#pragma unroll
    for (int a = 0; a < 4; a++)
#pragma unroll
        for (int b = 0; b < 4; b++)
#pragma unroll
            for (int c = 0; c < 4; c++) acc[a][b][c] = 0.f;

    const int nch = K / 32;

    auto load_chunk = [&](int c, int st) {
        const int k0 = c * 32;
        const uint32_t sb = ub + (uint32_t)st * GST;
#pragma unroll
        for (int i = 0; i < 2; i++) {
            int u = tid + i * 256;
            int row = u >> 2;
            int q   = u & 3;
            uint32_t so = (uint32_t)(row * 80 + q * 16);
            size_t goA = (size_t)(bm + row) * K + k0 + q * 8;
            size_t goB = (size_t)(bn + row) * K + k0 + q * 8;
            cp_async16(sb + so,             Ah + goA);
            cp_async16(sb + GARR + so,      Al + goA);
            cp_async16(sb + 2 * GARR + so,  Bh + goB);
            cp_async16(sb + 3 * GARR + so,  Bl + goB);
        }
    };

    load_chunk(0, 0);
    cp_commit();

    for (int c = 0; c < nch; c++) {
        const int st = c & 1;
        cp_wait<0>();           // chunk c resident
        __syncthreads();        // all warps done with chunk c-1 (stage st^1)
        if (c + 1 < nch) {
            load_chunk(c + 1, st ^ 1);   // safe: stage st^1 fully drained
            cp_commit();
        }

        const uint32_t sb = ub + (uint32_t)st * GST;
#pragma unroll
        for (int ks = 0; ks < 2; ks++) {
            const uint32_t kb = (uint32_t)(ks * 32);
            uint32_t ah[4][4], al[4][4], bh[4][2], bl[4][2];
#pragma unroll
            for (int mt = 0; mt < 4; mt++) {
                uint32_t base = (uint32_t)((wm * 64 + mt * 16) * 80) + kb + a_off;
                ldsm_x4(ah[mt][0], ah[mt][1], ah[mt][2], ah[mt][3], sb + base);
                ldsm_x4(al[mt][0], al[mt][1], al[mt][2], al[mt][3], sb + GARR + base);
            }
#pragma unroll
            for (int ntp = 0; ntp < 2; ntp++) {
                uint32_t base = (uint32_t)((wn * 32 + ntp * 16) * 80) + kb + b_off;
                ldsm_x4(bh[2 * ntp][0], bh[2 * ntp][1], bh[2 * ntp + 1][0], bh[2 * ntp + 1][1],
                        sb + 2 * GARR + base);
                ldsm_x4(bl[2 * ntp][0], bl[2 * ntp][1], bl[2 * ntp + 1][0], bl[2 * ntp + 1][1],
                        sb + 3 * GARR + base);
            }
#pragma unroll
            for (int mt = 0; mt < 4; mt++)
#pragma unroll
                for (int nt = 0; nt < 4; nt++) {
                    mma16816(acc[mt][nt], ah[mt][0], ah[mt][1], ah[mt][2], ah[mt][3],
                             bh[nt][0], bh[nt][1]);
                    mma16816(acc[mt][nt], ah[mt][0], ah[mt][1], ah[mt][2], ah[mt][3],
                             bl[nt][0], bl[nt][1]);
                    mma16816(acc[mt][nt], al[mt][0], al[mt][1], al[mt][2], al[mt][3],
                             bh[nt][0], bh[nt][1]);
                }
        }
    }

    if constexpr (!FUSED) {
#pragma unroll
        for (int mt = 0; mt < 4; mt++) {
            int row = bm + wm * 64 + mt * 16 + gq;
#pragma unroll
            for (int nt = 0; nt < 4; nt++) {
                int col = bn + wn * 32 + nt * 8 + 2 * tg;
                *(float2*)(C + (size_t)row * N + col) =
                    make_float2(acc[mt][nt][0], acc[mt][nt][1]);
                *(float2*)(C + (size_t)(row + 8) * N + col) =
                    make_float2(acc[mt][nt][2], acc[mt][nt][3]);
            }
        }
        return;
    } else {
        const int slot = bn >> 7;   // head slot 0..31 (0-15 q, 16-23 k, 24-31 v)

        if (slot >= 24) {
            const int vh = slot - 24;
#pragma unroll
            for (int mt = 0; mt < 4; mt++) {
#pragma unroll
                for (int hhalf = 0; hhalf < 2; hhalf++) {
                    int r = wm * 64 + mt * 16 + gq + 8 * hhalf;
                    int t = bm + r;
#pragma unroll
                    for (int nt = 0; nt < 4; nt++) {
                        int cn = wn * 32 + nt * 8 + 2 * tg;
                        size_t o = (size_t)t * KVW + vh * DH + cn;
                        split2_store(acc[mt][nt][2 * hhalf], acc[mt][nt][2 * hhalf + 1],
                                     vsh + o, vsl + o);
                    }
                }
            }
            return;
        }

        // Q/K: RMSNorm + RoPE(table) + split
        float* xs   = (float*)blob;              // [128][132] fp32 (67584 B)
        float* sums = (float*)(blob + 67584);    // [128][4] (outside last stage's reads)

#pragma unroll
        for (int mt = 0; mt < 4; mt++) {
#pragma unroll
            for (int hhalf = 0; hhalf < 2; hhalf++) {
                float p = 0.f;
#pragma unroll
                for (int nt = 0; nt < 4; nt++) {
                    float v0 = acc[mt][nt][2 * hhalf];
                    float v1 = acc[mt][nt][2 * hhalf + 1];
                    p += v0 * v0 + v1 * v1;
                }
                p += __shfl_xor_sync(0xffffffffu, p, 1);
                p += __shfl_xor_sync(0xffffffffu, p, 2);
                if (tg == 0) {
                    int r = wm * 64 + mt * 16 + gq + 8 * hhalf;
                    sums[r * 4 + wn] = p;
                }
            }
        }
        __syncthreads();

        const float* wvec = (slot < NH) ? qw : kw;
        float wcol[8];
#pragma unroll
        for (int nt = 0; nt < 4; nt++) {
            int cn = wn * 32 + nt * 8 + 2 * tg;
            wcol[2 * nt]     = wvec[cn];
            wcol[2 * nt + 1] = wvec[cn + 1];
        }
#pragma unroll
        for (int mt = 0; mt < 4; mt++) {
#pragma unroll
            for (int hhalf = 0; hhalf < 2; hhalf++) {
                int r = wm * 64 + mt * 16 + gq + 8 * hhalf;
                float ssum = sums[r * 4 + 0] + sums[r * 4 + 1] + sums[r * 4 + 2] + sums[r * 4 + 3];
                float rinv = rsqrtf(ssum * (1.f / DH) + EPS);
#pragma unroll
                for (int nt = 0; nt < 4; nt++) {
                    int cn = wn * 32 + nt * 8 + 2 * tg;
                    xs[r * 132 + cn]     = acc[mt][nt][2 * hhalf] * rinv * wcol[2 * nt];
                    xs[r * 132 + cn + 1] = acc[mt][nt][2 * hhalf + 1] * rinv * wcol[2 * nt + 1];
                }
            }
        }
        __syncthreads();

        const bool isq = (slot < NH);
        const float qscale = 0.08838834764831845f;   // 1/sqrt(128)
#pragma unroll
        for (int mt = 0; mt < 4; mt++) {
#pragma unroll
            for (int hhalf = 0; hhalf < 2; hhalf++) {
                int r = wm * 64 + mt * 16 + gq + 8 * hhalf;
                int t = bm + r;
#pragma unroll
                for (int nt = 0; nt < 4; nt++) {
                    int cn = wn * 32 + nt * 8 + 2 * tg;
                    int d  = cn & 63;
                    float x0 = xs[r * 132 + cn];
                    float x1 = xs[r * 132 + cn + 1];
                    float p0 = xs[r * 132 + (cn ^ 64)];
                    float p1 = xs[r * 132 + (cn ^ 64) + 1];
                    float2 cs0 = rope[t * 64 + d];
                    float2 cs1 = rope[t * 64 + d + 1];
                    float o0, o1;
                    if (cn < 64) {
                        o0 = x0 * cs0.x - p0 * cs0.y;
                        o1 = x1 * cs1.x - p1 * cs1.y;
                    } else {
                        o0 = x0 * cs0.x + p0 * cs0.y;
                        o1 = x1 * cs1.x + p1 * cs1.y;
                    }
                    if (isq) { o0 *= qscale; o1 *= qscale; }
                    if (isq) {
                        size_t o = (size_t)t * QW + slot * DH + cn;
                        split2_store(o0, o1, qsh + o, qsl + o);
                    } else {
                        size_t o = (size_t)t * KVW + (slot - NH) * DH + cn;
                        split2_store(o0, o1, ksh + o, ksl + o);
                    }
                }
            }
        }
    }
}

// ---------------------------------------------------------------------------
// FA2-style causal GQA attention, bf16x3 mma, in-register softmax.
// 3-stage cp.async pipeline (Q smem recycled as stage 2), ONE barrier/tile.
// ---------------------------------------------------------------------------
#define AT_BM 128
#define AT_BN 64
#define AT_ARR   17408    // bytes per array per stage (64 rows x 272B)
#define AT_STG   69632    // bytes per stage (Kh,Kl,Vh,Vl)
#define ATTN_SMEM (3 * AT_STG)   // 208896

__global__ __launch_bounds__(256, 1) void attn_kernel(
    const __nv_bfloat16* __restrict__ qsh, const __nv_bfloat16* __restrict__ qsl,
    const __nv_bfloat16* __restrict__ ksh, const __nv_bfloat16* __restrict__ ksl,
    const __nv_bfloat16* __restrict__ vsh, const __nv_bfloat16* __restrict__ vsl,
    __nv_bfloat16* __restrict__ oh, __nv_bfloat16* __restrict__ ol)
{
    extern __shared__ __align__(16) char asmem[];

    const int h   = blockIdx.x;
    const int m0  = (gridDim.y - 1 - blockIdx.y) * AT_BM;  // heavy blocks first
    const int kvh = h >> 1;
    const int tid = threadIdx.x;
    const int lane = tid & 31;
    const int w    = tid >> 5;
    const int gq   = lane >> 2;
    const int tg   = lane & 3;

    const uint32_t ub = su32(asmem);
    const uint32_t uS[3] = { ub, ub + AT_STG, ub + 2 * AT_STG };

    const uint32_t a_off = (uint32_t)((lane & 15) * 272 + (lane & 16));
    const uint32_t b_off = (uint32_t)(((lane & 7) + ((lane >> 4) << 3)) * 272 + (((lane >> 3) & 1) << 4));
    const uint32_t vlane_off = (uint32_t)((lane & 15) * 272 + ((lane >> 4) << 4));

    // cp.async prefetch of one 64-key tile into stage st
    auto prefetch = [&](int n0, int st) {
        const uint32_t sb = uS[st];
#pragma unroll
        for (int i = 0; i < 4; i++) {
            int u = tid + i * 256;
            int row = u >> 4;
            int c   = u & 15;
            uint32_t so = (uint32_t)(row * 272 + c * 16);
            size_t go = (size_t)(n0 + row) * KVW + kvh * DH + c * 8;
            cp_async16(sb + so,              ksh + go);
            cp_async16(sb + AT_ARR + so,     ksl + go);
            cp_async16(sb + 2 * AT_ARR + so, vsh + go);
            cp_async16(sb + 3 * AT_ARR + so, vsl + go);
        }
    };

    const int n_tiles = (m0 + AT_BM) / AT_BN;   // >= 2 always

    // Prologue: tiles 0,1 -> stages 0,1 (separate commit groups)
    prefetch(0, 0);
    cp_commit();
    prefetch(AT_BN, 1);
    cp_commit();

    // Q tile -> stage 2 smem (plain stores), then hoist to registers
    {
        const uint32_t qb = uS[2];
        for (int u = tid; u < AT_BM * 16; u += 256) {
            int row = u >> 4;
            int c   = u & 15;
            size_t go = (size_t)(m0 + row) * QW + h * DH + c * 8;
            uint32_t so = (uint32_t)(row * 272 + c * 16);
            *(uint4*)(asmem + (qb - ub) + so)          = *(const uint4*)(qsh + go);
            *(uint4*)(asmem + (qb - ub) + 34816 + so)  = *(const uint4*)(qsl + go);
        }
    }
    __syncthreads();   // Q stores visible for ldmatrix

    uint32_t qfh[8][4], qfl[8][4];
#pragma unroll
    for (int ks = 0; ks < 8; ks++) {
        uint32_t qbase = (uint32_t)(w * 16 * 272 + ks * 32) + a_off;
        ldsm_x4(qfh[ks][0], qfh[ks][1], qfh[ks][2], qfh[ks][3], uS[2] + qbase);
        ldsm_x4(qfl[ks][0], qfl[ks][1], qfl[ks][2], qfl[ks][3], uS[2] + 34816 + qbase);
    }

    float m_[2] = { -CUDART_INF_F, -CUDART_INF_F };
    float l_[2] = { 0.f, 0.f };

    float accO[16][4];
#pragma unroll
    for (int a = 0; a < 16; a++)
#pragma unroll
        for (int c = 0; c < 4; c++) accO[a][c] = 0.f;

    const int row0 = m0 + w * 16 + gq;

    for (int tile = 0; tile < n_tiles; tile++) {
        const int n0 = tile * AT_BN;
        const int st = tile % 3;

        // wait for tile's group: groups committed so far = min(tile+2, n_tiles)
        if (tile + 2 <= n_tiles) cp_wait<1>();
        else                     cp_wait<0>();
        __syncthreads();   // all warps done with tile-1 (stage (tile-1)%3 = (tile+2)%3)

        if (tile + 2 < n_tiles) {
            prefetch(n0 + 2 * AT_BN, (tile + 2) % 3);   // safe: that stage is drained
            cp_commit();
        }

        const uint32_t kh  = uS[st];
        const uint32_t kl  = uS[st] + AT_ARR;
        const uint32_t svh = uS[st] + 2 * AT_ARR;
        const uint32_t svl = uS[st] + 3 * AT_ARR;

        // ---- S = Q @ K^T (bf16x3), warp tile 16x64 ----
        float accS[8][4];
#pragma unroll
        for (int bb = 0; bb < 8; bb++)
#pragma unroll
            for (int c = 0; c < 4; c++) accS[bb][c] = 0.f;

#pragma unroll
        for (int ks = 0; ks < 8; ks++) {
            const uint32_t kb = (uint32_t)(ks * 32);
#pragma unroll
            for (int ntp = 0; ntp < 4; ntp++) {
                uint32_t base = (uint32_t)(ntp * 16 * 272) + kb + b_off;
                uint32_t bh0, bh1, bh2, bh3, bl0, bl1, bl2, bl3;
                ldsm_x4(bh0, bh1, bh2, bh3, kh + base);
                ldsm_x4(bl0, bl1, bl2, bl3, kl + base);
                mma16816(accS[2 * ntp],     qfh[ks][0], qfh[ks][1], qfh[ks][2], qfh[ks][3], bh0, bh1);
                mma16816(accS[2 * ntp],     qfh[ks][0], qfh[ks][1], qfh[ks][2], qfh[ks][3], bl0, bl1);
                mma16816(accS[2 * ntp],     qfl[ks][0], qfl[ks][1], qfl[ks][2], qfl[ks][3], bh0, bh1);
                mma16816(accS[2 * ntp + 1], qfh[ks][0], qfh[ks][1], qfh[ks][2], qfh[ks][3], bh2, bh3);
                mma16816(accS[2 * ntp + 1], qfh[ks][0], qfh[ks][1], qfh[ks][2], qfh[ks][3], bl2, bl3);
                mma16816(accS[2 * ntp + 1], qfl[ks][0], qfl[ks][1], qfl[ks][2], qfl[ks][3], bh2, bh3);
            }
        }

        // ---- causal mask ----
        if (n0 + AT_BN - 1 > m0) {
#pragma unroll
            for (int nt = 0; nt < 8; nt++) {
                int c0 = n0 + nt * 8 + 2 * tg;
                if (c0     > row0)     accS[nt][0] = -CUDART_INF_F;
                if (c0 + 1 > row0)     accS[nt][1] = -CUDART_INF_F;
                if (c0     > row0 + 8) accS[nt][2] = -CUDART_INF_F;
                if (c0 + 1 > row0 + 8) accS[nt][3] = -CUDART_INF_F;
            }
        }

        // ---- in-register online softmax ----
        float mx0 = accS[0][0], mx1 = accS[0][2];
#pragma unroll
        for (int nt = 0; nt < 8; nt++) {
            mx0 = fmaxf(mx0, fmaxf(accS[nt][0], accS[nt][1]));
            mx1 = fmaxf(mx1, fmaxf(accS[nt][2], accS[nt][3]));
        }
        mx0 = fmaxf(mx0, __shfl_xor_sync(0xffffffffu, mx0, 1));
        mx0 = fmaxf(mx0, __shfl_xor_sync(0xffffffffu, mx0, 2));
        mx1 = fmaxf(mx1, __shfl_xor_sync(0xffffffffu, mx1, 1));
        mx1 = fmaxf(mx1, __shfl_xor_sync(0xffffffffu, mx1, 2));

        float mn0 = fmaxf(m_[0], mx0);
        float mn1 = fmaxf(m_[1], mx1);
        float corr0 = __expf(m_[0] - mn0);
        float corr1 = __expf(m_[1] - mn1);
        float sum0 = 0.f, sum1 = 0.f;
#pragma unroll
        for (int nt = 0; nt < 8; nt++) {
            accS[nt][0] = __expf(accS[nt][0] - mn0);
            accS[nt][1] = __expf(accS[nt][1] - mn0);
            accS[nt][2] = __expf(accS[nt][2] - mn1);
            accS[nt][3] = __expf(accS[nt][3] - mn1);
            sum0 += accS[nt][0] + accS[nt][1];
            sum1 += accS[nt][2] + accS[nt][3];
        }
        sum0 += __shfl_xor_sync(0xffffffffu, sum0, 1);
        sum0 += __shfl_xor_sync(0xffffffffu, sum0, 2);
        sum1 += __shfl_xor_sync(0xffffffffu, sum1, 1);
        sum1 += __shfl_xor_sync(0xffffffffu, sum1, 2);
        l_[0] = l_[0] * corr0 + sum0;
        l_[1] = l_[1] * corr1 + sum1;
        m_[0] = mn0; m_[1] = mn1;

#pragma unroll
        for (int nt = 0; nt < 16; nt++) {
            accO[nt][0] *= corr0; accO[nt][1] *= corr0;
            accO[nt][2] *= corr1; accO[nt][3] *= corr1;
        }

        // ---- O += P @ V (bf16x3), warp tile 16x128, k=64 ----
#pragma unroll
        for (int kc = 0; kc < 4; kc++) {
            float p00 = accS[2 * kc][0],     p01 = accS[2 * kc][1];
            float p10 = accS[2 * kc][2],     p11 = accS[2 * kc][3];
            float p20 = accS[2 * kc + 1][0], p21 = accS[2 * kc + 1][1];
            float p30 = accS[2 * kc + 1][2], p31 = accS[2 * kc + 1][3];
            float h00 = __bfloat162float(__float2bfloat16(p00));
            float h01 = __bfloat162float(__float2bfloat16(p01));
            float h10 = __bfloat162float(__float2bfloat16(p10));
            float h11 = __bfloat162float(__float2bfloat16(p11));
            float h20 = __bfloat162float(__float2bfloat16(p20));
            float h21 = __bfloat162float(__float2bfloat16(p21));
            float h30 = __bfloat162float(__float2bfloat16(p30));
            float h31 = __bfloat162float(__float2bfloat16(p31));
            uint32_t ph0 = pack_bf16x2(h00, h01);
            uint32_t ph1 = pack_bf16x2(h10, h11);
            uint32_t ph2 = pack_bf16x2(h20, h21);
            uint32_t ph3 = pack_bf16x2(h30, h31);
            uint32_t pl0 = pack_bf16x2(p00 - h00, p01 - h01);
            uint32_t pl1 = pack_bf16x2(p10 - h10, p11 - h11);
            uint32_t pl2 = pack_bf16x2(p20 - h20, p21 - h21);
            uint32_t pl3 = pack_bf16x2(p30 - h30, p31 - h31);

#pragma unroll
            for (int ncg = 0; ncg < 8; ncg++) {
                uint32_t base_off = (uint32_t)(kc * 16 * 272 + ncg * 32) + vlane_off;
                uint32_t vh0, vh1, vh2, vh3, vl0, vl1, vl2, vl3;
                ldsm_x4_t(vh0, vh1, vh2, vh3, svh + base_off);
                ldsm_x4_t(vl0, vl1, vl2, vl3, svl + base_off);
                mma16816(accO[ncg * 2],     ph0, ph1, ph2, ph3, vh0, vh1);
                mma16816(accO[ncg * 2],     ph0, ph1, ph2, ph3, vl0, vl1);
                mma16816(accO[ncg * 2],     pl0, pl1, pl2, pl3, vh0, vh1);
                mma16816(accO[ncg * 2 + 1], ph0, ph1, ph2, ph3, vh2, vh3);
                mma16816(accO[ncg * 2 + 1], ph0, ph1, ph2, ph3, vl2, vl3);
                mma16816(accO[ncg * 2 + 1], pl0, pl1, pl2, pl3, vh2, vh3);
            }
        }
    }

    // ---- normalize + split-write bf16 hi/lo ----
    float i0 = 1.f / l_[0];
    float i1 = 1.f / l_[1];
#pragma unroll
    for (int nt = 0; nt < 16; nt++) {
        int col = h * DH + nt * 8 + 2 * tg;
        float v0 = accO[nt][0] * i0, v1 = accO[nt][1] * i0;
        float v2 = accO[nt][2] * i1, v3 = accO[nt][3] * i1;
        size_t o0 = (size_t)row0 * HID + col;
        size_t o1 = (size_t)(row0 + 8) * HID + col;
        split2_store(v0, v1, oh + o0, ol + o0);
        split2_store(v2, v3, oh + o1, ol + o1);
    }
}

// ---------------------------------------------------------------------------
// Launch
// ---------------------------------------------------------------------------
extern "C" void kernel_launch(void* const* d_in, const int* in_sizes, int n_in,
                              void* d_out, int out_size)
{
    const int*   positions = (const int*)d_in[0];
    const float* hidden    = (const float*)d_in[1];
    const float* w_qkv     = (const float*)d_in[2];
    const float* w_o       = (const float*)d_in[3];
    const float* q_norm_w  = (const float*)d_in[4];
    const float* k_norm_w  = (const float*)d_in[5];
    float*       out       = (float*)d_out;

    __nv_bfloat16 *ah, *al, *bh, *bl, *qsh, *qsl, *ksh, *ksl, *vsh, *vsl;
    float2* rope;
    cudaGetSymbolAddress((void**)&ah, g_ah);
    cudaGetSymbolAddress((void**)&al, g_al);
    cudaGetSymbolAddress((void**)&bh, g_bh);
    cudaGetSymbolAddress((void**)&bl, g_bl);
    cudaGetSymbolAddress((void**)&qsh, g_qsh);
    cudaGetSymbolAddress((void**)&qsl, g_qsl);
    cudaGetSymbolAddress((void**)&ksh, g_ksh);
    cudaGetSymbolAddress((void**)&ksl, g_ksl);
    cudaGetSymbolAddress((void**)&vsh, g_vsh);
    cudaGetSymbolAddress((void**)&vsl, g_vsl);
    cudaGetSymbolAddress((void**)&rope, g_rope);

    cudaFuncSetAttribute(gemm_mma_kernel_t<true>,
                         cudaFuncAttributeMaxDynamicSharedMemorySize, GEMM_SMEM);
    cudaFuncSetAttribute(gemm_mma_kernel_t<false>,
                         cudaFuncAttributeMaxDynamicSharedMemorySize, GEMM_SMEM);
    cudaFuncSetAttribute(attn_kernel,
                         cudaFuncAttributeMaxDynamicSharedMemorySize, ATTN_SMEM);

    // 1. Split hidden (+ build RoPE table); transpose+split w_qkv.
    {
        int n = TT * HID;
        split_kernel<<<n / 4 / 256, 256>>>(hidden, ah, al, n, positions, rope);
        dim3 tg(QKVW / 32, HID / 32);
        transpose_split_kernel<<<tg, dim3(32, 8)>>>(w_qkv, bh, bl, HID, QKVW);
    }

    // 2. QKV projection with FUSED norm/rope/split epilogue (2 CTAs/SM).
    {
        dim3 grid(QKVW / 128, TT / 128);
        gemm_mma_kernel_t<true><<<grid, 256, GEMM_SMEM>>>(
            TT, QKVW, HID, ah, al, bh, bl,
            nullptr, rope, q_norm_w, k_norm_w,
            qsh, qsl, ksh, ksl, vsh, vsl);
    }

    // 3. Causal GQA flash attention (3-stage pipeline);
    //    writes split bf16 hi/lo into ah/al.
    {
        dim3 grid(NH, TT / AT_BM);
        attn_kernel<<<grid, 256, ATTN_SMEM>>>(
            qsh, qsl, ksh, ksl, vsh, vsl, ah, al);
    }

    // 4. transpose+split w_o (only needed before O-proj; bh/bl free now).
    {
        dim3 tg(HID / 32, (NH * DH) / 32);
        transpose_split_kernel<<<tg, dim3(32, 8)>>>(w_o, bh, bl, NH * DH, HID);
    }

    // 5. Output projection (plain fp32 epilogue, 2 CTAs/SM).
    {
        dim3 grid(HID / 128, TT / 128);
        gemm_mma_kernel_t<false><<<grid, 256, GEMM_SMEM>>>(
            TT, HID, NH * DH, ah, al, bh, bl,
            out, nullptr, nullptr, nullptr,
            nullptr, nullptr, nullptr, nullptr, nullptr, nullptr);
    }
}

// round 13
// speedup vs baseline: 1.0533x; 1.0533x over previous
#include <cuda_runtime.h>
#include <cuda_bf16.h>
#include <math.h>
#include <math_constants.h>
#include <stdint.h>

// Problem constants
#define TT   2048
#define HID  2048
#define NH   16
#define NKV  8
#define DH   128
#define QKVW ((NH + 2 * NKV) * DH)   // 4096
#define QW   (NH * DH)               // 2048
#define KVW  (NKV * DH)              // 1024
#define EPS  1e-6f

// Scratch (allocation-free rule: __device__ globals)
__device__ __nv_bfloat16 g_ah[(size_t)TT * HID];     // GEMM A hi / attn-out hi
__device__ __nv_bfloat16 g_al[(size_t)TT * HID];     // GEMM A lo / attn-out lo
__device__ __nv_bfloat16 g_bh[(size_t)QKVW * HID];   // B^T hi ([N,K])
__device__ __nv_bfloat16 g_bl[(size_t)QKVW * HID];   // B^T lo
__device__ __nv_bfloat16 g_qsh[(size_t)TT * QW],  g_qsl[(size_t)TT * QW];   // split Q (scaled)
__device__ __nv_bfloat16 g_ksh[(size_t)TT * KVW], g_ksl[(size_t)TT * KVW];  // split K
__device__ __nv_bfloat16 g_vsh[(size_t)TT * KVW], g_vsl[(size_t)TT * KVW];  // split V
__device__ float2 g_rope[(size_t)TT * 64];           // (cos, sin) per (t, d)

// ---------------------------------------------------------------------------
// PTX helpers (base sm_103 target — HMMA mma.sync + ldmatrix + cp.async)
// ---------------------------------------------------------------------------
__device__ __forceinline__ void mma16816(float d[4],
                                         uint32_t a0, uint32_t a1, uint32_t a2, uint32_t a3,
                                         uint32_t b0, uint32_t b1)
{
    asm volatile(
        "mma.sync.aligned.m16n8k16.row.col.f32.bf16.bf16.f32 "
        "{%0,%1,%2,%3}, {%4,%5,%6,%7}, {%8,%9}, {%0,%1,%2,%3};\n"
        : "+f"(d[0]), "+f"(d[1]), "+f"(d[2]), "+f"(d[3])
        : "r"(a0), "r"(a1), "r"(a2), "r"(a3), "r"(b0), "r"(b1));
}

__device__ __forceinline__ void ldsm_x4(uint32_t& r0, uint32_t& r1,
                                        uint32_t& r2, uint32_t& r3, uint32_t addr)
{
    asm volatile("ldmatrix.sync.aligned.m8n8.x4.shared.b16 {%0,%1,%2,%3}, [%4];"
                 : "=r"(r0), "=r"(r1), "=r"(r2), "=r"(r3) : "r"(addr));
}

__device__ __forceinline__ void ldsm_x4_t(uint32_t& r0, uint32_t& r1,
                                          uint32_t& r2, uint32_t& r3, uint32_t addr)
{
    asm volatile("ldmatrix.sync.aligned.m8n8.x4.trans.shared.b16 {%0,%1,%2,%3}, [%4];"
                 : "=r"(r0), "=r"(r1), "=r"(r2), "=r"(r3) : "r"(addr));
}

__device__ __forceinline__ uint32_t su32(const void* p) {
    return (uint32_t)__cvta_generic_to_shared(p);
}

__device__ __forceinline__ uint32_t pack_bf16x2(float a, float b) {
    __nv_bfloat162 t = __floats2bfloat162_rn(a, b);
    return *(uint32_t*)&t;
}

__device__ __forceinline__ void cp_async16(uint32_t dst, const void* src) {
    asm volatile("cp.async.cg.shared.global [%0], [%1], 16;" :: "r"(dst), "l"(src));
}
__device__ __forceinline__ void cp_commit() {
    asm volatile("cp.async.commit_group;" ::: "memory");
}
template <int N>
__device__ __forceinline__ void cp_wait() {
    asm volatile("cp.async.wait_group %0;" :: "n"(N) : "memory");
}

// hi/lo split of a float4, stored as 2x bf162 each
__device__ __forceinline__ void split4_store(float4 v, __nv_bfloat16* hp, __nv_bfloat16* lp) {
    __nv_bfloat16 h0 = __float2bfloat16(v.x), h1 = __float2bfloat16(v.y);
    __nv_bfloat16 h2 = __float2bfloat16(v.z), h3 = __float2bfloat16(v.w);
    *(uint32_t*)(hp)     = pack_bf16x2(__bfloat162float(h0), __bfloat162float(h1));
    *(uint32_t*)(hp + 2) = pack_bf16x2(__bfloat162float(h2), __bfloat162float(h3));
    *(uint32_t*)(lp)     = pack_bf16x2(v.x - __bfloat162float(h0), v.y - __bfloat162float(h1));
    *(uint32_t*)(lp + 2) = pack_bf16x2(v.z - __bfloat162float(h2), v.w - __bfloat162float(h3));
}

// hi/lo split of 2 floats -> two u32 stores
__device__ __forceinline__ void split2_store(float a, float b,
                                             __nv_bfloat16* hp, __nv_bfloat16* lp) {
    float ha = __bfloat162float(__float2bfloat16(a));
    float hb = __bfloat162float(__float2bfloat16(b));
    *(uint32_t*)hp = pack_bf16x2(ha, hb);
    *(uint32_t*)lp = pack_bf16x2(a - ha, b - hb);
}

// ---------------------------------------------------------------------------
// Split conversion (+ RoPE table build by the first TT*64 threads).
// ---------------------------------------------------------------------------
__global__ __launch_bounds__(256) void split_kernel(
    const float* __restrict__ x,
    __nv_bfloat16* __restrict__ hi, __nv_bfloat16* __restrict__ lo, int n,
    const int* __restrict__ positions, float2* __restrict__ rope)
{
    int j = blockIdx.x * blockDim.x + threadIdx.x;
    if (rope && j < TT * 64) {
        int t = j >> 6;
        int d = j & 63;
        float pos = (float)positions[t];
        float inv_freq = powf(10000.f, -(float)d * (1.f / 64.f));
        float sv, cv;
        sincosf(pos * inv_freq, &sv, &cv);
        rope[j] = make_float2(cv, sv);
    }
    int i = j * 4;
    if (i >= n) return;
    float4 v = *(const float4*)(x + i);
    split4_store(v, hi + i, lo + i);
}

// ---------------------------------------------------------------------------
// Transpose + split: W[K,N] fp32 -> Th/Tl [N,K] bf16. K,N % 32 == 0.
// ---------------------------------------------------------------------------
__global__ __launch_bounds__(256) void transpose_split_kernel(
    const float* __restrict__ W,
    __nv_bfloat16* __restrict__ Th, __nv_bfloat16* __restrict__ Tl,
    int K, int N)
{
    __shared__ float tile[32][33];
    const int bn = blockIdx.x * 32;
    const int bk = blockIdx.y * 32;
    const int tx = threadIdx.x;
    const int ty = threadIdx.y;
#pragma unroll
    for (int j = 0; j < 32; j += 8)
        tile[ty + j][tx] = W[(size_t)(bk + ty + j) * N + bn + tx];
    __syncthreads();
#pragma unroll
    for (int j = 0; j < 32; j += 8) {
        float v = tile[tx][ty + j];
        __nv_bfloat16 h = __float2bfloat16(v);
        __nv_bfloat16 l = __float2bfloat16(v - __bfloat162float(h));
        size_t o = (size_t)(bn + ty + j) * K + bk + tx;
        Th[o] = h;
        Tl[o] = l;
    }
}

// ---------------------------------------------------------------------------
// mma.sync bf16x3 GEMM (R11 mainloop: prefetch-early, wait<1>):
// cp.async double-buffered, ldmatrix frags, dynamic smem 80 KB, 2 CTAs/SM.
// FUSED=true: QKV projection with RMSNorm+RoPE(table)+split epilogue.
// ---------------------------------------------------------------------------
#define GST   10240   // bytes per stage per array (128 rows x 80B)
#define GARR  20480   // bytes per array (2 stages)
#define GEMM_SMEM 81920

template<bool FUSED>
__global__ __launch_bounds__(256, 2) void gemm_mma_kernel_t(
    int M, int N, int K,
    const __nv_bfloat16* __restrict__ Ah, const __nv_bfloat16* __restrict__ Al,
    const __nv_bfloat16* __restrict__ Bh, const __nv_bfloat16* __restrict__ Bl,
    float* __restrict__ C,
    const float2* __restrict__ rope,
    const float* __restrict__ qw, const float* __restrict__ kw,
    __nv_bfloat16* __restrict__ qsh, __nv_bfloat16* __restrict__ qsl,
    __nv_bfloat16* __restrict__ ksh, __nv_bfloat16* __restrict__ ksl,
    __nv_bfloat16* __restrict__ vsh, __nv_bfloat16* __restrict__ vsl)
{
    extern __shared__ __align__(16) char blob[];

    const int tid  = threadIdx.x;
    const int lane = tid & 31;
    const int wid  = tid >> 5;
    const int wm   = wid >> 2;
    const int wn   = wid & 3;
    const int gq   = lane >> 2;
    const int tg   = lane & 3;
    const int bm = blockIdx.y * 128;
    const int bn = blockIdx.x * 128;

    const uint32_t ub = su32(blob);
    const uint32_t a_off = (uint32_t)((lane & 15) * 80 + (lane & 16));
    const uint32_t b_off = (uint32_t)(((lane & 7) + ((lane >> 4) << 3)) * 80 + (((lane >> 3) & 1) << 4));

    float acc[4][4][4];
#pragma unroll
    for (int a = 0; a < 4; a++)
#pragma unroll
        for (int b = 0; b < 4; b++)
#pragma unroll
            for (int c = 0; c < 4; c++) acc[a][b][c] = 0.f;

    const int nch = K / 32;

    auto load_chunk = [&](int c, int st) {
        const int k0 = c * 32;
        const uint32_t sb = ub + (uint32_t)st * GST;
#pragma unroll
        for (int i = 0; i < 2; i++) {
            int u = tid + i * 256;
            int row = u >> 2;
            int q   = u & 3;
            uint32_t so = (uint32_t)(row * 80 + q * 16);
            size_t goA = (size_t)(bm + row) * K + k0 + q * 8;
            size_t goB = (size_t)(bn + row) * K + k0 + q * 8;
            cp_async16(sb + so,             Ah + goA);
            cp_async16(sb + GARR + so,      Al + goA);
            cp_async16(sb + 2 * GARR + so,  Bh + goB);
            cp_async16(sb + 3 * GARR + so,  Bl + goB);
        }
    };

    load_chunk(0, 0);
    cp_commit();

    for (int c = 0; c < nch; c++) {
        const int st = c & 1;
        if (c + 1 < nch) {
            load_chunk(c + 1, st ^ 1);   // issue early: overlaps wait below
            cp_commit();
            cp_wait<1>();                // chunk c resident; c+1 may be in flight
        } else {
            cp_wait<0>();
        }
        __syncthreads();

        const uint32_t sb = ub + (uint32_t)st * GST;
#pragma unroll
        for (int ks = 0; ks < 2; ks++) {
            const uint32_t kb = (uint32_t)(ks * 32);
            uint32_t ah[4][4], al[4][4], bh[4][2], bl[4][2];
#pragma unroll
            for (int mt = 0; mt < 4; mt++) {
                uint32_t base = (uint32_t)((wm * 64 + mt * 16) * 80) + kb + a_off;
                ldsm_x4(ah[mt][0], ah[mt][1], ah[mt][2], ah[mt][3], sb + base);
                ldsm_x4(al[mt][0], al[mt][1], al[mt][2], al[mt][3], sb + GARR + base);
            }
#pragma unroll
            for (int ntp = 0; ntp < 2; ntp++) {
                uint32_t base = (uint32_t)((wn * 32 + ntp * 16) * 80) + kb + b_off;
                ldsm_x4(bh[2 * ntp][0], bh[2 * ntp][1], bh[2 * ntp + 1][0], bh[2 * ntp + 1][1],
                        sb + 2 * GARR + base);
                ldsm_x4(bl[2 * ntp][0], bl[2 * ntp][1], bl[2 * ntp + 1][0], bl[2 * ntp + 1][1],
                        sb + 3 * GARR + base);
            }
#pragma unroll
            for (int mt = 0; mt < 4; mt++)
#pragma unroll
                for (int nt = 0; nt < 4; nt++) {
                    mma16816(acc[mt][nt], ah[mt][0], ah[mt][1], ah[mt][2], ah[mt][3],
                             bh[nt][0], bh[nt][1]);
                    mma16816(acc[mt][nt], ah[mt][0], ah[mt][1], ah[mt][2], ah[mt][3],
                             bl[nt][0], bl[nt][1]);
                    mma16816(acc[mt][nt], al[mt][0], al[mt][1], al[mt][2], al[mt][3],
                             bh[nt][0], bh[nt][1]);
                }
        }
        __syncthreads();   // all reads of stage st done before it's refilled
    }

    if constexpr (!FUSED) {
#pragma unroll
        for (int mt = 0; mt < 4; mt++) {
            int row = bm + wm * 64 + mt * 16 + gq;
#pragma unroll
            for (int nt = 0; nt < 4; nt++) {
                int col = bn + wn * 32 + nt * 8 + 2 * tg;
                *(float2*)(C + (size_t)row * N + col) =
                    make_float2(acc[mt][nt][0], acc[mt][nt][1]);
                *(float2*)(C + (size_t)(row + 8) * N + col) =
                    make_float2(acc[mt][nt][2], acc[mt][nt][3]);
            }
        }
        return;
    } else {
        const int slot = bn >> 7;   // head slot 0..31 (0-15 q, 16-23 k, 24-31 v)

        if (slot >= 24) {
            const int vh = slot - 24;
#pragma unroll
            for (int mt = 0; mt < 4; mt++) {
#pragma unroll
                for (int hhalf = 0; hhalf < 2; hhalf++) {
                    int r = wm * 64 + mt * 16 + gq + 8 * hhalf;
                    int t = bm + r;
#pragma unroll
                    for (int nt = 0; nt < 4; nt++) {
                        int cn = wn * 32 + nt * 8 + 2 * tg;
                        size_t o = (size_t)t * KVW + vh * DH + cn;
                        split2_store(acc[mt][nt][2 * hhalf], acc[mt][nt][2 * hhalf + 1],
                                     vsh + o, vsl + o);
                    }
                }
            }
            return;
        }

        // Q/K: RMSNorm + RoPE(table) + split
        float* xs   = (float*)blob;              // [128][132] fp32 (67584 B)
        float* sums = (float*)(blob + 67584);    // [128][4]

#pragma unroll
        for (int mt = 0; mt < 4; mt++) {
#pragma unroll
            for (int hhalf = 0; hhalf < 2; hhalf++) {
                float p = 0.f;
#pragma unroll
                for (int nt = 0; nt < 4; nt++) {
                    float v0 = acc[mt][nt][2 * hhalf];
                    float v1 = acc[mt][nt][2 * hhalf + 1];
                    p += v0 * v0 + v1 * v1;
                }
                p += __shfl_xor_sync(0xffffffffu, p, 1);
                p += __shfl_xor_sync(0xffffffffu, p, 2);
                if (tg == 0) {
                    int r = wm * 64 + mt * 16 + gq + 8 * hhalf;
                    sums[r * 4 + wn] = p;
                }
            }
        }
        __syncthreads();

        const float* wvec = (slot < NH) ? qw : kw;
        float wcol[8];
#pragma unroll
        for (int nt = 0; nt < 4; nt++) {
            int cn = wn * 32 + nt * 8 + 2 * tg;
            wcol[2 * nt]     = wvec[cn];
            wcol[2 * nt + 1] = wvec[cn + 1];
        }
#pragma unroll
        for (int mt = 0; mt < 4; mt++) {
#pragma unroll
            for (int hhalf = 0; hhalf < 2; hhalf++) {
                int r = wm * 64 + mt * 16 + gq + 8 * hhalf;
                float ssum = sums[r * 4 + 0] + sums[r * 4 + 1] + sums[r * 4 + 2] + sums[r * 4 + 3];
                float rinv = rsqrtf(ssum * (1.f / DH) + EPS);
#pragma unroll
                for (int nt = 0; nt < 4; nt++) {
                    int cn = wn * 32 + nt * 8 + 2 * tg;
                    xs[r * 132 + cn]     = acc[mt][nt][2 * hhalf] * rinv * wcol[2 * nt];
                    xs[r * 132 + cn + 1] = acc[mt][nt][2 * hhalf + 1] * rinv * wcol[2 * nt + 1];
                }
            }
        }
        __syncthreads();

        const bool isq = (slot < NH);
        const float qscale = 0.08838834764831845f;   // 1/sqrt(128)
#pragma unroll
        for (int mt = 0; mt < 4; mt++) {
#pragma unroll
            for (int hhalf = 0; hhalf < 2; hhalf++) {
                int r = wm * 64 + mt * 16 + gq + 8 * hhalf;
                int t = bm + r;
#pragma unroll
                for (int nt = 0; nt < 4; nt++) {
                    int cn = wn * 32 + nt * 8 + 2 * tg;
                    int d  = cn & 63;
                    float x0 = xs[r * 132 + cn];
                    float x1 = xs[r * 132 + cn + 1];
                    float p0 = xs[r * 132 + (cn ^ 64)];
                    float p1 = xs[r * 132 + (cn ^ 64) + 1];
                    float2 cs0 = rope[t * 64 + d];
                    float2 cs1 = rope[t * 64 + d + 1];
                    float o0, o1;
                    if (cn < 64) {
                        o0 = x0 * cs0.x - p0 * cs0.y;
                        o1 = x1 * cs1.x - p1 * cs1.y;
                    } else {
                        o0 = x0 * cs0.x + p0 * cs0.y;
                        o1 = x1 * cs1.x + p1 * cs1.y;
                    }
                    if (isq) { o0 *= qscale; o1 *= qscale; }
                    if (isq) {
                        size_t o = (size_t)t * QW + slot * DH + cn;
                        split2_store(o0, o1, qsh + o, qsl + o);
                    } else {
                        size_t o = (size_t)t * KVW + (slot - NH) * DH + cn;
                        split2_store(o0, o1, ksh + o, ksl + o);
                    }
                }
            }
        }
    }
}

// ---------------------------------------------------------------------------
// FA2-style causal GQA attention, bf16x3 mma, in-register softmax.
// 3-stage cp.async pipeline (Q smem recycled as stage 2), one barrier/tile.
// ---------------------------------------------------------------------------
#define AT_BM 128
#define AT_BN 64
#define AT_ARR   17408    // bytes per array per stage (64 rows x 272B)
#define AT_STG   69632    // bytes per stage (Kh,Kl,Vh,Vl)
#define ATTN_SMEM (3 * AT_STG)   // 208896

__global__ __launch_bounds__(256, 1) void attn_kernel(
    const __nv_bfloat16* __restrict__ qsh, const __nv_bfloat16* __restrict__ qsl,
    const __nv_bfloat16* __restrict__ ksh, const __nv_bfloat16* __restrict__ ksl,
    const __nv_bfloat16* __restrict__ vsh, const __nv_bfloat16* __restrict__ vsl,
    __nv_bfloat16* __restrict__ oh, __nv_bfloat16* __restrict__ ol)
{
    extern __shared__ __align__(16) char asmem[];

    const int h   = blockIdx.x;
    const int m0  = (gridDim.y - 1 - blockIdx.y) * AT_BM;  // heavy blocks first
    const int kvh = h >> 1;
    const int tid = threadIdx.x;
    const int lane = tid & 31;
    const int w    = tid >> 5;
    const int gq   = lane >> 2;
    const int tg   = lane & 3;

    const uint32_t ub = su32(asmem);
    const uint32_t uS[3] = { ub, ub + AT_STG, ub + 2 * AT_STG };

    const uint32_t a_off = (uint32_t)((lane & 15) * 272 + (lane & 16));
    const uint32_t b_off = (uint32_t)(((lane & 7) + ((lane >> 4) << 3)) * 272 + (((lane >> 3) & 1) << 4));
    const uint32_t vlane_off = (uint32_t)((lane & 15) * 272 + ((lane >> 4) << 4));

    auto prefetch = [&](int n0, int st) {
        const uint32_t sb = uS[st];
#pragma unroll
        for (int i = 0; i < 4; i++) {
            int u = tid + i * 256;
            int row = u >> 4;
            int c   = u & 15;
            uint32_t so = (uint32_t)(row * 272 + c * 16);
            size_t go = (size_t)(n0 + row) * KVW + kvh * DH + c * 8;
            cp_async16(sb + so,              ksh + go);
            cp_async16(sb + AT_ARR + so,     ksl + go);
            cp_async16(sb + 2 * AT_ARR + so, vsh + go);
            cp_async16(sb + 3 * AT_ARR + so, vsl + go);
        }
    };

    const int n_tiles = (m0 + AT_BM) / AT_BN;   // >= 2 always

    prefetch(0, 0);
    cp_commit();
    prefetch(AT_BN, 1);
    cp_commit();

    // Q tile -> stage 2 smem (plain stores), then hoist to registers
    {
        const uint32_t qrel = 2 * AT_STG;
        for (int u = tid; u < AT_BM * 16; u += 256) {
            int row = u >> 4;
            int c   = u & 15;
            size_t go = (size_t)(m0 + row) * QW + h * DH + c * 8;
            uint32_t so = (uint32_t)(row * 272 + c * 16);
            *(uint4*)(asmem + qrel + so)         = *(const uint4*)(qsh + go);
            *(uint4*)(asmem + qrel + 34816 + so) = *(const uint4*)(qsl + go);
        }
    }
    __syncthreads();

    uint32_t qfh[8][4], qfl[8][4];
#pragma unroll
    for (int ks = 0; ks < 8; ks++) {
        uint32_t qbase = (uint32_t)(w * 16 * 272 + ks * 32) + a_off;
        ldsm_x4(qfh[ks][0], qfh[ks][1], qfh[ks][2], qfh[ks][3], uS[2] + qbase);
        ldsm_x4(qfl[ks][0], qfl[ks][1], qfl[ks][2], qfl[ks][3], uS[2] + 34816 + qbase);
    }

    float m_[2] = { -CUDART_INF_F, -CUDART_INF_F };
    float l_[2] = { 0.f, 0.f };

    float accO[16][4];
#pragma unroll
    for (int a = 0; a < 16; a++)
#pragma unroll
        for (int c = 0; c < 4; c++) accO[a][c] = 0.f;

    const int row0 = m0 + w * 16 + gq;

    for (int tile = 0; tile < n_tiles; tile++) {
        const int n0 = tile * AT_BN;
        const int st = tile % 3;

        if (tile + 2 <= n_tiles) cp_wait<1>();
        else                     cp_wait<0>();
        __syncthreads();   // all warps done with tile-1 (stage (tile+2)%3)

        if (tile + 2 < n_tiles) {
            prefetch(n0 + 2 * AT_BN, (tile + 2) % 3);   // stage drained by barrier
            cp_commit();
        }

        const uint32_t kh  = uS[st];
        const uint32_t kl  = uS[st] + AT_ARR;
        const uint32_t svh = uS[st] + 2 * AT_ARR;
        const uint32_t svl = uS[st] + 3 * AT_ARR;

        // ---- S = Q @ K^T (bf16x3), warp tile 16x64 ----
        float accS[8][4];
#pragma unroll
        for (int bb = 0; bb < 8; bb++)
#pragma unroll
            for (int c = 0; c < 4; c++) accS[bb][c] = 0.f;

#pragma unroll
        for (int ks = 0; ks < 8; ks++) {
            const uint32_t kb = (uint32_t)(ks * 32);
#pragma unroll
            for (int ntp = 0; ntp < 4; ntp++) {
                uint32_t base = (uint32_t)(ntp * 16 * 272) + kb + b_off;
                uint32_t bh0, bh1, bh2, bh3, bl0, bl1, bl2, bl3;
                ldsm_x4(bh0, bh1, bh2, bh3, kh + base);
                ldsm_x4(bl0, bl1, bl2, bl3, kl + base);
                mma16816(accS[2 * ntp],     qfh[ks][0], qfh[ks][1], qfh[ks][2], qfh[ks][3], bh0, bh1);
                mma16816(accS[2 * ntp],     qfh[ks][0], qfh[ks][1], qfh[ks][2], qfh[ks][3], bl0, bl1);
                mma16816(accS[2 * ntp],     qfl[ks][0], qfl[ks][1], qfl[ks][2], qfl[ks][3], bh0, bh1);
                mma16816(accS[2 * ntp + 1], qfh[ks][0], qfh[ks][1], qfh[ks][2], qfh[ks][3], bh2, bh3);
                mma16816(accS[2 * ntp + 1], qfh[ks][0], qfh[ks][1], qfh[ks][2], qfh[ks][3], bl2, bl3);
                mma16816(accS[2 * ntp + 1], qfl[ks][0], qfl[ks][1], qfl[ks][2], qfl[ks][3], bh2, bh3);
            }
        }

        // ---- causal mask ----
        if (n0 + AT_BN - 1 > m0) {
#pragma unroll
            for (int nt = 0; nt < 8; nt++) {
                int c0 = n0 + nt * 8 + 2 * tg;
                if (c0     > row0)     accS[nt][0] = -CUDART_INF_F;
                if (c0 + 1 > row0)     accS[nt][1] = -CUDART_INF_F;
                if (c0     > row0 + 8) accS[nt][2] = -CUDART_INF_F;
                if (c0 + 1 > row0 + 8) accS[nt][3] = -CUDART_INF_F;
            }
        }

        // ---- in-register online softmax ----
        float mx0 = accS[0][0], mx1 = accS[0][2];
#pragma unroll
        for (int nt = 0; nt < 8; nt++) {
            mx0 = fmaxf(mx0, fmaxf(accS[nt][0], accS[nt][1]));
            mx1 = fmaxf(mx1, fmaxf(accS[nt][2], accS[nt][3]));
        }
        mx0 = fmaxf(mx0, __shfl_xor_sync(0xffffffffu, mx0, 1));
        mx0 = fmaxf(mx0, __shfl_xor_sync(0xffffffffu, mx0, 2));
        mx1 = fmaxf(mx1, __shfl_xor_sync(0xffffffffu, mx1, 1));
        mx1 = fmaxf(mx1, __shfl_xor_sync(0xffffffffu, mx1, 2));

        float mn0 = fmaxf(m_[0], mx0);
        float mn1 = fmaxf(m_[1], mx1);
        float corr0 = __expf(m_[0] - mn0);
        float corr1 = __expf(m_[1] - mn1);
        float sum0 = 0.f, sum1 = 0.f;
#pragma unroll
        for (int nt = 0; nt < 8; nt++) {
            accS[nt][0] = __expf(accS[nt][0] - mn0);
            accS[nt][1] = __expf(accS[nt][1] - mn0);
            accS[nt][2] = __expf(accS[nt][2] - mn1);
            accS[nt][3] = __expf(accS[nt][3] - mn1);
            sum0 += accS[nt][0] + accS[nt][1];
            sum1 += accS[nt][2] + accS[nt][3];
        }
        sum0 += __shfl_xor_sync(0xffffffffu, sum0, 1);
        sum0 += __shfl_xor_sync(0xffffffffu, sum0, 2);
        sum1 += __shfl_xor_sync(0xffffffffu, sum1, 1);
        sum1 += __shfl_xor_sync(0xffffffffu, sum1, 2);
        l_[0] = l_[0] * corr0 + sum0;
        l_[1] = l_[1] * corr1 + sum1;
        m_[0] = mn0; m_[1] = mn1;

#pragma unroll
        for (int nt = 0; nt < 16; nt++) {
            accO[nt][0] *= corr0; accO[nt][1] *= corr0;
            accO[nt][2] *= corr1; accO[nt][3] *= corr1;
        }

        // ---- O += P @ V (bf16x3), warp tile 16x128, k=64 ----
#pragma unroll
        for (int kc = 0; kc < 4; kc++) {
            float p00 = accS[2 * kc][0],     p01 = accS[2 * kc][1];
            float p10 = accS[2 * kc][2],     p11 = accS[2 * kc][3];
            float p20 = accS[2 * kc + 1][0], p21 = accS[2 * kc + 1][1];
            float p30 = accS[2 * kc + 1][2], p31 = accS[2 * kc + 1][3];
            float h00 = __bfloat162float(__float2bfloat16(p00));
            float h01 = __bfloat162float(__float2bfloat16(p01));
            float h10 = __bfloat162float(__float2bfloat16(p10));
            float h11 = __bfloat162float(__float2bfloat16(p11));
            float h20 = __bfloat162float(__float2bfloat16(p20));
            float h21 = __bfloat162float(__float2bfloat16(p21));
            float h30 = __bfloat162float(__float2bfloat16(p30));
            float h31 = __bfloat162float(__float2bfloat16(p31));
            uint32_t ph0 = pack_bf16x2(h00, h01);
            uint32_t ph1 = pack_bf16x2(h10, h11);
            uint32_t ph2 = pack_bf16x2(h20, h21);
            uint32_t ph3 = pack_bf16x2(h30, h31);
            uint32_t pl0 = pack_bf16x2(p00 - h00, p01 - h01);
            uint32_t pl1 = pack_bf16x2(p10 - h10, p11 - h11);
            uint32_t pl2 = pack_bf16x2(p20 - h20, p21 - h21);
            uint32_t pl3 = pack_bf16x2(p30 - h30, p31 - h31);

#pragma unroll
            for (int ncg = 0; ncg < 8; ncg++) {
                uint32_t base_off = (uint32_t)(kc * 16 * 272 + ncg * 32) + vlane_off;
                uint32_t vh0, vh1, vh2, vh3, vl0, vl1, vl2, vl3;
                ldsm_x4_t(vh0, vh1, vh2, vh3, svh + base_off);
                ldsm_x4_t(vl0, vl1, vl2, vl3, svl + base_off);
                mma16816(accO[ncg * 2],     ph0, ph1, ph2, ph3, vh0, vh1);
                mma16816(accO[ncg * 2],     ph0, ph1, ph2, ph3, vl0, vl1);
                mma16816(accO[ncg * 2],     pl0, pl1, pl2, pl3, vh0, vh1);
                mma16816(accO[ncg * 2 + 1], ph0, ph1, ph2, ph3, vh2, vh3);
                mma16816(accO[ncg * 2 + 1], ph0, ph1, ph2, ph3, vl2, vl3);
                mma16816(accO[ncg * 2 + 1], pl0, pl1, pl2, pl3, vh2, vh3);
            }
        }
    }

    // ---- normalize + split-write bf16 hi/lo ----
    float i0 = 1.f / l_[0];
    float i1 = 1.f / l_[1];
#pragma unroll
    for (int nt = 0; nt < 16; nt++) {
        int col = h * DH + nt * 8 + 2 * tg;
        float v0 = accO[nt][0] * i0, v1 = accO[nt][1] * i0;
        float v2 = accO[nt][2] * i1, v3 = accO[nt][3] * i1;
        size_t o0 = (size_t)row0 * HID + col;
        size_t o1 = (size_t)(row0 + 8) * HID + col;
        split2_store(v0, v1, oh + o0, ol + o0);
        split2_store(v2, v3, oh + o1, ol + o1);
    }
}

// ---------------------------------------------------------------------------
// Launch
// ---------------------------------------------------------------------------
extern "C" void kernel_launch(void* const* d_in, const int* in_sizes, int n_in,
                              void* d_out, int out_size)
{
    const int*   positions = (const int*)d_in[0];
    const float* hidden    = (const float*)d_in[1];
    const float* w_qkv     = (const float*)d_in[2];
    const float* w_o       = (const float*)d_in[3];
    const float* q_norm_w  = (const float*)d_in[4];
    const float* k_norm_w  = (const float*)d_in[5];
    float*       out       = (float*)d_out;

    __nv_bfloat16 *ah, *al, *bh, *bl, *qsh, *qsl, *ksh, *ksl, *vsh, *vsl;
    float2* rope;
    cudaGetSymbolAddress((void**)&ah, g_ah);
    cudaGetSymbolAddress((void**)&al, g_al);
    cudaGetSymbolAddress((void**)&bh, g_bh);
    cudaGetSymbolAddress((void**)&bl, g_bl);
    cudaGetSymbolAddress((void**)&qsh, g_qsh);
    cudaGetSymbolAddress((void**)&qsl, g_qsl);
    cudaGetSymbolAddress((void**)&ksh, g_ksh);
    cudaGetSymbolAddress((void**)&ksl, g_ksl);
    cudaGetSymbolAddress((void**)&vsh, g_vsh);
    cudaGetSymbolAddress((void**)&vsl, g_vsl);
    cudaGetSymbolAddress((void**)&rope, g_rope);

    cudaFuncSetAttribute(gemm_mma_kernel_t<true>,
                         cudaFuncAttributeMaxDynamicSharedMemorySize, GEMM_SMEM);
    cudaFuncSetAttribute(gemm_mma_kernel_t<false>,
                         cudaFuncAttributeMaxDynamicSharedMemorySize, GEMM_SMEM);
    cudaFuncSetAttribute(attn_kernel,
                         cudaFuncAttributeMaxDynamicSharedMemorySize, ATTN_SMEM);

    // 1. Split hidden (+ build RoPE table); transpose+split w_qkv.
    {
        int n = TT * HID;
        split_kernel<<<n / 4 / 256, 256>>>(hidden, ah, al, n, positions, rope);
        dim3 tg(QKVW / 32, HID / 32);
        transpose_split_kernel<<<tg, dim3(32, 8)>>>(w_qkv, bh, bl, HID, QKVW);
    }

    // 2. QKV projection with FUSED norm/rope/split epilogue (2 CTAs/SM).
    {
        dim3 grid(QKVW / 128, TT / 128);
        gemm_mma_kernel_t<true><<<grid, 256, GEMM_SMEM>>>(
            TT, QKVW, HID, ah, al, bh, bl,
            nullptr, rope, q_norm_w, k_norm_w,
            qsh, qsl, ksh, ksl, vsh, vsl);
    }

    // 3. Causal GQA flash attention (3-stage pipeline);
    //    writes split bf16 hi/lo into ah/al.
    {
        dim3 grid(NH, TT / AT_BM);
        attn_kernel<<<grid, 256, ATTN_SMEM>>>(
            qsh, qsl, ksh, ksl, vsh, vsl, ah, al);
    }

    // 4. transpose+split w_o (only needed before O-proj; bh/bl free now).
    {
        dim3 tg(HID / 32, (NH * DH) / 32);
        transpose_split_kernel<<<tg, dim3(32, 8)>>>(w_o, bh, bl, NH * DH, HID);
    }

    // 5. Output projection (plain fp32 epilogue, 2 CTAs/SM).
    {
        dim3 grid(HID / 128, TT / 128);
        gemm_mma_kernel_t<false><<<grid, 256, GEMM_SMEM>>>(
            TT, HID, NH * DH, ah, al, bh, bl,
            out, nullptr, nullptr, nullptr,
            nullptr, nullptr, nullptr, nullptr, nullptr, nullptr);
    }
}

// round 14
// speedup vs baseline: 1.2690x; 1.2048x over previous
#include <cuda_runtime.h>
#include <cuda_bf16.h>
#include <cuda_fp16.h>
#include <math.h>
#include <math_constants.h>
#include <stdint.h>

// Problem constants
#define TT   2048
#define HID  2048
#define NH   16
#define NKV  8
#define DH   128
#define QKVW ((NH + 2 * NKV) * DH)   // 4096
#define QW   (NH * DH)               // 2048
#define KVW  (NKV * DH)              // 1024
#define EPS  1e-6f

// Scratch (allocation-free rule: __device__ globals)
__device__ __half g_ah[(size_t)TT * HID];            // GEMM A hi (fp16) / attn-out hi
__device__ __half g_al[(size_t)TT * HID];            // GEMM A lo (fp16) / attn-out lo
__device__ __half g_bh[(size_t)QKVW * HID];          // B^T single fp16 ([N,K])
__device__ __nv_bfloat16 g_qsh[(size_t)TT * QW],  g_qsl[(size_t)TT * QW];   // split Q (scaled, bf16)
__device__ __nv_bfloat16 g_ksh[(size_t)TT * KVW], g_ksl[(size_t)TT * KVW];  // split K (bf16)
__device__ __nv_bfloat16 g_vsh[(size_t)TT * KVW], g_vsl[(size_t)TT * KVW];  // split V (bf16)
__device__ float2 g_rope[(size_t)TT * 64];           // (cos, sin) per (t, d)

// ---------------------------------------------------------------------------
// PTX helpers (base sm_103 target — HMMA mma.sync + ldmatrix + cp.async)
// ---------------------------------------------------------------------------
__device__ __forceinline__ void mma16816(float d[4],
                                         uint32_t a0, uint32_t a1, uint32_t a2, uint32_t a3,
                                         uint32_t b0, uint32_t b1)
{
    asm volatile(
        "mma.sync.aligned.m16n8k16.row.col.f32.bf16.bf16.f32 "
        "{%0,%1,%2,%3}, {%4,%5,%6,%7}, {%8,%9}, {%0,%1,%2,%3};\n"
        : "+f"(d[0]), "+f"(d[1]), "+f"(d[2]), "+f"(d[3])
        : "r"(a0), "r"(a1), "r"(a2), "r"(a3), "r"(b0), "r"(b1));
}

__device__ __forceinline__ void mma16816h(float d[4],
                                          uint32_t a0, uint32_t a1, uint32_t a2, uint32_t a3,
                                          uint32_t b0, uint32_t b1)
{
    asm volatile(
        "mma.sync.aligned.m16n8k16.row.col.f32.f16.f16.f32 "
        "{%0,%1,%2,%3}, {%4,%5,%6,%7}, {%8,%9}, {%0,%1,%2,%3};\n"
        : "+f"(d[0]), "+f"(d[1]), "+f"(d[2]), "+f"(d[3])
        : "r"(a0), "r"(a1), "r"(a2), "r"(a3), "r"(b0), "r"(b1));
}

__device__ __forceinline__ void ldsm_x4(uint32_t& r0, uint32_t& r1,
                                        uint32_t& r2, uint32_t& r3, uint32_t addr)
{
    asm volatile("ldmatrix.sync.aligned.m8n8.x4.shared.b16 {%0,%1,%2,%3}, [%4];"
                 : "=r"(r0), "=r"(r1), "=r"(r2), "=r"(r3) : "r"(addr));
}

__device__ __forceinline__ void ldsm_x4_t(uint32_t& r0, uint32_t& r1,
                                          uint32_t& r2, uint32_t& r3, uint32_t addr)
{
    asm volatile("ldmatrix.sync.aligned.m8n8.x4.trans.shared.b16 {%0,%1,%2,%3}, [%4];"
                 : "=r"(r0), "=r"(r1), "=r"(r2), "=r"(r3) : "r"(addr));
}

__device__ __forceinline__ uint32_t su32(const void* p) {
    return (uint32_t)__cvta_generic_to_shared(p);
}

__device__ __forceinline__ uint32_t pack_bf16x2(float a, float b) {
    __nv_bfloat162 t = __floats2bfloat162_rn(a, b);
    return *(uint32_t*)&t;
}

__device__ __forceinline__ uint32_t pack_h2(float a, float b) {
    __half2 t = __floats2half2_rn(a, b);
    return *(uint32_t*)&t;
}

__device__ __forceinline__ void cp_async16(uint32_t dst, const void* src) {
    asm volatile("cp.async.cg.shared.global [%0], [%1], 16;" :: "r"(dst), "l"(src));
}
__device__ __forceinline__ void cp_commit() {
    asm volatile("cp.async.commit_group;" ::: "memory");
}
template <int N>
__device__ __forceinline__ void cp_wait() {
    asm volatile("cp.async.wait_group %0;" :: "n"(N) : "memory");
}

// bf16 hi/lo split of 2 floats -> two u32 stores
__device__ __forceinline__ void split2_store(float a, float b,
                                             __nv_bfloat16* hp, __nv_bfloat16* lp) {
    float ha = __bfloat162float(__float2bfloat16(a));
    float hb = __bfloat162float(__float2bfloat16(b));
    *(uint32_t*)hp = pack_bf16x2(ha, hb);
    *(uint32_t*)lp = pack_bf16x2(a - ha, b - hb);
}

// fp16 hi/lo split of 2 floats -> two u32 stores
__device__ __forceinline__ void split2h_store(float a, float b,
                                              __half* hp, __half* lp) {
    float ha = __half2float(__float2half_rn(a));
    float hb = __half2float(__float2half_rn(b));
    *(uint32_t*)hp = pack_h2(ha, hb);
    *(uint32_t*)lp = pack_h2(a - ha, b - hb);
}

// ---------------------------------------------------------------------------
// Split conversion fp32 -> fp16 hi/lo (+ RoPE table build).
// ---------------------------------------------------------------------------
__global__ __launch_bounds__(256) void split_kernel(
    const float* __restrict__ x,
    __half* __restrict__ hi, __half* __restrict__ lo, int n,
    const int* __restrict__ positions, float2* __restrict__ rope)
{
    int j = blockIdx.x * blockDim.x + threadIdx.x;
    if (rope && j < TT * 64) {
        int t = j >> 6;
        int d = j & 63;
        float pos = (float)positions[t];
        float inv_freq = powf(10000.f, -(float)d * (1.f / 64.f));
        float sv, cv;
        sincosf(pos * inv_freq, &sv, &cv);
        rope[j] = make_float2(cv, sv);
    }
    int i = j * 4;
    if (i >= n) return;
    float4 v = *(const float4*)(x + i);
    split2h_store(v.x, v.y, hi + i, lo + i);
    split2h_store(v.z, v.w, hi + i + 2, lo + i + 2);
}

// ---------------------------------------------------------------------------
// Transpose to single fp16: W[K,N] fp32 -> Th [N,K] fp16. K,N % 32 == 0.
// ---------------------------------------------------------------------------
__global__ __launch_bounds__(256) void transpose_half_kernel(
    const float* __restrict__ W,
    __half* __restrict__ Th, int K, int N)
{
    __shared__ float tile[32][33];
    const int bn = blockIdx.x * 32;
    const int bk = blockIdx.y * 32;
    const int tx = threadIdx.x;
    const int ty = threadIdx.y;
#pragma unroll
    for (int j = 0; j < 32; j += 8)
        tile[ty + j][tx] = W[(size_t)(bk + ty + j) * N + bn + tx];
    __syncthreads();
#pragma unroll
    for (int j = 0; j < 32; j += 8) {
        Th[(size_t)(bn + ty + j) * K + bk + tx] = __float2half_rn(tile[tx][ty + j]);
    }
}

// ---------------------------------------------------------------------------
// mma.sync fp16x2 GEMM: C = A @ B with A = Ah+Al (fp16), B = Bh (fp16).
// 2 MMAs per step. cp.async double-buffered (prefetch-early), ldmatrix frags,
// dynamic smem, 2 CTAs/SM.
// FUSED=true: QKV projection with RMSNorm+RoPE(table)+bf16-split epilogue.
// ---------------------------------------------------------------------------
#define GST   10240   // bytes per stage per array (128 rows x 80B)
#define GARR  20480   // bytes per array (2 stages)
#define GEMM_SMEM 69632   // mainloop needs 61440; fused epilogue needs 67584+2048

template<bool FUSED>
__global__ __launch_bounds__(256, 2) void gemm_mma_kernel_t(
    int M, int N, int K,
    const __half* __restrict__ Ah, const __half* __restrict__ Al,
    const __half* __restrict__ Bh,
    float* __restrict__ C,
    const float2* __restrict__ rope,
    const float* __restrict__ qw, const float* __restrict__ kw,
    __nv_bfloat16* __restrict__ qsh, __nv_bfloat16* __restrict__ qsl,
    __nv_bfloat16* __restrict__ ksh, __nv_bfloat16* __restrict__ ksl,
    __nv_bfloat16* __restrict__ vsh, __nv_bfloat16* __restrict__ vsl)
{
    extern __shared__ __align__(16) char blob[];

    const int tid  = threadIdx.x;
    const int lane = tid & 31;
    const int wid  = tid >> 5;
    const int wm   = wid >> 2;
    const int wn   = wid & 3;
    const int gq   = lane >> 2;
    const int tg   = lane & 3;
    const int bm = blockIdx.y * 128;
    const int bn = blockIdx.x * 128;

    const uint32_t ub = su32(blob);
    const uint32_t a_off = (uint32_t)((lane & 15) * 80 + (lane & 16));
    const uint32_t b_off = (uint32_t)(((lane & 7) + ((lane >> 4) << 3)) * 80 + (((lane >> 3) & 1) << 4));

    float acc[4][4][4];
#pragma unroll
    for (int a = 0; a < 4; a++)
#pragma unroll
        for (int b = 0; b < 4; b++)
#pragma unroll
            for (int c = 0; c < 4; c++) acc[a][b][c] = 0.f;

    const int nch = K / 32;

    auto load_chunk = [&](int c, int st) {
        const int k0 = c * 32;
        const uint32_t sb = ub + (uint32_t)st * GST;
#pragma unroll
        for (int i = 0; i < 2; i++) {
            int u = tid + i * 256;
            int row = u >> 2;
            int q   = u & 3;
            uint32_t so = (uint32_t)(row * 80 + q * 16);
            size_t goA = (size_t)(bm + row) * K + k0 + q * 8;
            size_t goB = (size_t)(bn + row) * K + k0 + q * 8;
            cp_async16(sb + so,             Ah + goA);
            cp_async16(sb + GARR + so,      Al + goA);
            cp_async16(sb + 2 * GARR + so,  Bh + goB);
        }
    };

    load_chunk(0, 0);
    cp_commit();

    for (int c = 0; c < nch; c++) {
        const int st = c & 1;
        if (c + 1 < nch) {
            load_chunk(c + 1, st ^ 1);   // issue early: overlaps wait below
            cp_commit();
            cp_wait<1>();
        } else {
            cp_wait<0>();
        }
        __syncthreads();

        const uint32_t sb = ub + (uint32_t)st * GST;
#pragma unroll
        for (int ks = 0; ks < 2; ks++) {
            const uint32_t kb = (uint32_t)(ks * 32);
            uint32_t ah[4][4], al[4][4], bh[4][2];
#pragma unroll
            for (int mt = 0; mt < 4; mt++) {
                uint32_t base = (uint32_t)((wm * 64 + mt * 16) * 80) + kb + a_off;
                ldsm_x4(ah[mt][0], ah[mt][1], ah[mt][2], ah[mt][3], sb + base);
                ldsm_x4(al[mt][0], al[mt][1], al[mt][2], al[mt][3], sb + GARR + base);
            }
#pragma unroll
            for (int ntp = 0; ntp < 2; ntp++) {
                uint32_t base = (uint32_t)((wn * 32 + ntp * 16) * 80) + kb + b_off;
                ldsm_x4(bh[2 * ntp][0], bh[2 * ntp][1], bh[2 * ntp + 1][0], bh[2 * ntp + 1][1],
                        sb + 2 * GARR + base);
            }
#pragma unroll
            for (int mt = 0; mt < 4; mt++)
#pragma unroll
                for (int nt = 0; nt < 4; nt++) {
                    mma16816h(acc[mt][nt], ah[mt][0], ah[mt][1], ah[mt][2], ah[mt][3],
                              bh[nt][0], bh[nt][1]);
                    mma16816h(acc[mt][nt], al[mt][0], al[mt][1], al[mt][2], al[mt][3],
                              bh[nt][0], bh[nt][1]);
                }
        }
        __syncthreads();   // all reads of stage st done before it's refilled
    }

    if constexpr (!FUSED) {
#pragma unroll
        for (int mt = 0; mt < 4; mt++) {
            int row = bm + wm * 64 + mt * 16 + gq;
#pragma unroll
            for (int nt = 0; nt < 4; nt++) {
                int col = bn + wn * 32 + nt * 8 + 2 * tg;
                *(float2*)(C + (size_t)row * N + col) =
                    make_float2(acc[mt][nt][0], acc[mt][nt][1]);
                *(float2*)(C + (size_t)(row + 8) * N + col) =
                    make_float2(acc[mt][nt][2], acc[mt][nt][3]);
            }
        }
        return;
    } else {
        const int slot = bn >> 7;   // head slot 0..31 (0-15 q, 16-23 k, 24-31 v)

        if (slot >= 24) {
            const int vh = slot - 24;
#pragma unroll
            for (int mt = 0; mt < 4; mt++) {
#pragma unroll
                for (int hhalf = 0; hhalf < 2; hhalf++) {
                    int r = wm * 64 + mt * 16 + gq + 8 * hhalf;
                    int t = bm + r;
#pragma unroll
                    for (int nt = 0; nt < 4; nt++) {
                        int cn = wn * 32 + nt * 8 + 2 * tg;
                        size_t o = (size_t)t * KVW + vh * DH + cn;
                        split2_store(acc[mt][nt][2 * hhalf], acc[mt][nt][2 * hhalf + 1],
                                     vsh + o, vsl + o);
                    }
                }
            }
            return;
        }

        // Q/K: RMSNorm + RoPE(table) + bf16 split
        float* xs   = (float*)blob;              // [128][132] fp32 (67584 B)
        float* sums = (float*)(blob + 67584);    // [128][4]

#pragma unroll
        for (int mt = 0; mt < 4; mt++) {
#pragma unroll
            for (int hhalf = 0; hhalf < 2; hhalf++) {
                float p = 0.f;
#pragma unroll
                for (int nt = 0; nt < 4; nt++) {
                    float v0 = acc[mt][nt][2 * hhalf];
                    float v1 = acc[mt][nt][2 * hhalf + 1];
                    p += v0 * v0 + v1 * v1;
                }
                p += __shfl_xor_sync(0xffffffffu, p, 1);
                p += __shfl_xor_sync(0xffffffffu, p, 2);
                if (tg == 0) {
                    int r = wm * 64 + mt * 16 + gq + 8 * hhalf;
                    sums[r * 4 + wn] = p;
                }
            }
        }
        __syncthreads();

        const float* wvec = (slot < NH) ? qw : kw;
        float wcol[8];
#pragma unroll
        for (int nt = 0; nt < 4; nt++) {
            int cn = wn * 32 + nt * 8 + 2 * tg;
            wcol[2 * nt]     = wvec[cn];
            wcol[2 * nt + 1] = wvec[cn + 1];
        }
#pragma unroll
        for (int mt = 0; mt < 4; mt++) {
#pragma unroll
            for (int hhalf = 0; hhalf < 2; hhalf++) {
                int r = wm * 64 + mt * 16 + gq + 8 * hhalf;
                float ssum = sums[r * 4 + 0] + sums[r * 4 + 1] + sums[r * 4 + 2] + sums[r * 4 + 3];
                float rinv = rsqrtf(ssum * (1.f / DH) + EPS);
#pragma unroll
                for (int nt = 0; nt < 4; nt++) {
                    int cn = wn * 32 + nt * 8 + 2 * tg;
                    xs[r * 132 + cn]     = acc[mt][nt][2 * hhalf] * rinv * wcol[2 * nt];
                    xs[r * 132 + cn + 1] = acc[mt][nt][2 * hhalf + 1] * rinv * wcol[2 * nt + 1];
                }
            }
        }
        __syncthreads();

        const bool isq = (slot < NH);
        const float qscale = 0.08838834764831845f;   // 1/sqrt(128)
#pragma unroll
        for (int mt = 0; mt < 4; mt++) {
#pragma unroll
            for (int hhalf = 0; hhalf < 2; hhalf++) {
                int r = wm * 64 + mt * 16 + gq + 8 * hhalf;
                int t = bm + r;
#pragma unroll
                for (int nt = 0; nt < 4; nt++) {
                    int cn = wn * 32 + nt * 8 + 2 * tg;
                    int d  = cn & 63;
                    float x0 = xs[r * 132 + cn];
                    float x1 = xs[r * 132 + cn + 1];
                    float p0 = xs[r * 132 + (cn ^ 64)];
                    float p1 = xs[r * 132 + (cn ^ 64) + 1];
                    float2 cs0 = rope[t * 64 + d];
                    float2 cs1 = rope[t * 64 + d + 1];
                    float o0, o1;
                    if (cn < 64) {
                        o0 = x0 * cs0.x - p0 * cs0.y;
                        o1 = x1 * cs1.x - p1 * cs1.y;
                    } else {
                        o0 = x0 * cs0.x + p0 * cs0.y;
                        o1 = x1 * cs1.x + p1 * cs1.y;
                    }
                    if (isq) { o0 *= qscale; o1 *= qscale; }
                    if (isq) {
                        size_t o = (size_t)t * QW + slot * DH + cn;
                        split2_store(o0, o1, qsh + o, qsl + o);
                    } else {
                        size_t o = (size_t)t * KVW + (slot - NH) * DH + cn;
                        split2_store(o0, o1, ksh + o, ksl + o);
                    }
                }
            }
        }
    }
}

// ---------------------------------------------------------------------------
// FA2-style causal GQA attention, bf16x3 mma, in-register softmax.
// 3-stage cp.async pipeline (Q smem recycled as stage 2).
// Epilogue writes fp16 hi/lo (feeds the fp16x2 O-projection).
// ---------------------------------------------------------------------------
#define AT_BM 128
#define AT_BN 64
#define AT_ARR   17408    // bytes per array per stage (64 rows x 272B)
#define AT_STG   69632    // bytes per stage (Kh,Kl,Vh,Vl)
#define ATTN_SMEM (3 * AT_STG)   // 208896

__global__ __launch_bounds__(256, 1) void attn_kernel(
    const __nv_bfloat16* __restrict__ qsh, const __nv_bfloat16* __restrict__ qsl,
    const __nv_bfloat16* __restrict__ ksh, const __nv_bfloat16* __restrict__ ksl,
    const __nv_bfloat16* __restrict__ vsh, const __nv_bfloat16* __restrict__ vsl,
    __half* __restrict__ oh, __half* __restrict__ ol)
{
    extern __shared__ __align__(16) char asmem[];

    const int h   = blockIdx.x;
    const int m0  = (gridDim.y - 1 - blockIdx.y) * AT_BM;  // heavy blocks first
    const int kvh = h >> 1;
    const int tid = threadIdx.x;
    const int lane = tid & 31;
    const int w    = tid >> 5;
    const int gq   = lane >> 2;
    const int tg   = lane & 3;

    const uint32_t ub = su32(asmem);
    const uint32_t uS[3] = { ub, ub + AT_STG, ub + 2 * AT_STG };

    const uint32_t a_off = (uint32_t)((lane & 15) * 272 + (lane & 16));
    const uint32_t b_off = (uint32_t)(((lane & 7) + ((lane >> 4) << 3)) * 272 + (((lane >> 3) & 1) << 4));
    const uint32_t vlane_off = (uint32_t)((lane & 15) * 272 + ((lane >> 4) << 4));

    auto prefetch = [&](int n0, int st) {
        const uint32_t sb = uS[st];
#pragma unroll
        for (int i = 0; i < 4; i++) {
            int u = tid + i * 256;
            int row = u >> 4;
            int c   = u & 15;
            uint32_t so = (uint32_t)(row * 272 + c * 16);
            size_t go = (size_t)(n0 + row) * KVW + kvh * DH + c * 8;
            cp_async16(sb + so,              ksh + go);
            cp_async16(sb + AT_ARR + so,     ksl + go);
            cp_async16(sb + 2 * AT_ARR + so, vsh + go);
            cp_async16(sb + 3 * AT_ARR + so, vsl + go);
        }
    };

    const int n_tiles = (m0 + AT_BM) / AT_BN;   // >= 2 always

    prefetch(0, 0);
    cp_commit();
    prefetch(AT_BN, 1);
    cp_commit();

    // Q tile -> stage 2 smem (plain stores), then hoist to registers
    {
        const uint32_t qrel = 2 * AT_STG;
        for (int u = tid; u < AT_BM * 16; u += 256) {
            int row = u >> 4;
            int c   = u & 15;
            size_t go = (size_t)(m0 + row) * QW + h * DH + c * 8;
            uint32_t so = (uint32_t)(row * 272 + c * 16);
            *(uint4*)(asmem + qrel + so)         = *(const uint4*)(qsh + go);
            *(uint4*)(asmem + qrel + 34816 + so) = *(const uint4*)(qsl + go);
        }
    }
    __syncthreads();

    uint32_t qfh[8][4], qfl[8][4];
#pragma unroll
    for (int ks = 0; ks < 8; ks++) {
        uint32_t qbase = (uint32_t)(w * 16 * 272 + ks * 32) + a_off;
        ldsm_x4(qfh[ks][0], qfh[ks][1], qfh[ks][2], qfh[ks][3], uS[2] + qbase);
        ldsm_x4(qfl[ks][0], qfl[ks][1], qfl[ks][2], qfl[ks][3], uS[2] + 34816 + qbase);
    }

    float m_[2] = { -CUDART_INF_F, -CUDART_INF_F };
    float l_[2] = { 0.f, 0.f };

    float accO[16][4];
#pragma unroll
    for (int a = 0; a < 16; a++)
#pragma unroll
        for (int c = 0; c < 4; c++) accO[a][c] = 0.f;

    const int row0 = m0 + w * 16 + gq;

    for (int tile = 0; tile < n_tiles; tile++) {
        const int n0 = tile * AT_BN;
        const int st = tile % 3;

        if (tile + 2 <= n_tiles) cp_wait<1>();
        else                     cp_wait<0>();
        __syncthreads();

        if (tile + 2 < n_tiles) {
            prefetch(n0 + 2 * AT_BN, (tile + 2) % 3);
            cp_commit();
        }

        const uint32_t kh  = uS[st];
        const uint32_t kl  = uS[st] + AT_ARR;
        const uint32_t svh = uS[st] + 2 * AT_ARR;
        const uint32_t svl = uS[st] + 3 * AT_ARR;

        // ---- S = Q @ K^T (bf16x3), warp tile 16x64 ----
        float accS[8][4];
#pragma unroll
        for (int bb = 0; bb < 8; bb++)
#pragma unroll
            for (int c = 0; c < 4; c++) accS[bb][c] = 0.f;

#pragma unroll
        for (int ks = 0; ks < 8; ks++) {
            const uint32_t kb = (uint32_t)(ks * 32);
#pragma unroll
            for (int ntp = 0; ntp < 4; ntp++) {
                uint32_t base = (uint32_t)(ntp * 16 * 272) + kb + b_off;
                uint32_t bh0, bh1, bh2, bh3, bl0, bl1, bl2, bl3;
                ldsm_x4(bh0, bh1, bh2, bh3, kh + base);
                ldsm_x4(bl0, bl1, bl2, bl3, kl + base);
                mma16816(accS[2 * ntp],     qfh[ks][0], qfh[ks][1], qfh[ks][2], qfh[ks][3], bh0, bh1);
                mma16816(accS[2 * ntp],     qfh[ks][0], qfh[ks][1], qfh[ks][2], qfh[ks][3], bl0, bl1);
                mma16816(accS[2 * ntp],     qfl[ks][0], qfl[ks][1], qfl[ks][2], qfl[ks][3], bh0, bh1);
                mma16816(accS[2 * ntp + 1], qfh[ks][0], qfh[ks][1], qfh[ks][2], qfh[ks][3], bh2, bh3);
                mma16816(accS[2 * ntp + 1], qfh[ks][0], qfh[ks][1], qfh[ks][2], qfh[ks][3], bl2, bl3);
                mma16816(accS[2 * ntp + 1], qfl[ks][0], qfl[ks][1], qfl[ks][2], qfl[ks][3], bh2, bh3);
            }
        }

        // ---- causal mask ----
        if (n0 + AT_BN - 1 > m0) {
#pragma unroll
            for (int nt = 0; nt < 8; nt++) {
                int c0 = n0 + nt * 8 + 2 * tg;
                if (c0     > row0)     accS[nt][0] = -CUDART_INF_F;
                if (c0 + 1 > row0)     accS[nt][1] = -CUDART_INF_F;
                if (c0     > row0 + 8) accS[nt][2] = -CUDART_INF_F;
                if (c0 + 1 > row0 + 8) accS[nt][3] = -CUDART_INF_F;
            }
        }

        // ---- in-register online softmax ----
        float mx0 = accS[0][0], mx1 = accS[0][2];
#pragma unroll
        for (int nt = 0; nt < 8; nt++) {
            mx0 = fmaxf(mx0, fmaxf(accS[nt][0], accS[nt][1]));
            mx1 = fmaxf(mx1, fmaxf(accS[nt][2], accS[nt][3]));
        }
        mx0 = fmaxf(mx0, __shfl_xor_sync(0xffffffffu, mx0, 1));
        mx0 = fmaxf(mx0, __shfl_xor_sync(0xffffffffu, mx0, 2));
        mx1 = fmaxf(mx1, __shfl_xor_sync(0xffffffffu, mx1, 1));
        mx1 = fmaxf(mx1, __shfl_xor_sync(0xffffffffu, mx1, 2));

        float mn0 = fmaxf(m_[0], mx0);
        float mn1 = fmaxf(m_[1], mx1);
        float corr0 = __expf(m_[0] - mn0);
        float corr1 = __expf(m_[1] - mn1);
        float sum0 = 0.f, sum1 = 0.f;
#pragma unroll
        for (int nt = 0; nt < 8; nt++) {
            accS[nt][0] = __expf(accS[nt][0] - mn0);
            accS[nt][1] = __expf(accS[nt][1] - mn0);
            accS[nt][2] = __expf(accS[nt][2] - mn1);
            accS[nt][3] = __expf(accS[nt][3] - mn1);
            sum0 += accS[nt][0] + accS[nt][1];
            sum1 += accS[nt][2] + accS[nt][3];
        }
        sum0 += __shfl_xor_sync(0xffffffffu, sum0, 1);
        sum0 += __shfl_xor_sync(0xffffffffu, sum0, 2);
        sum1 += __shfl_xor_sync(0xffffffffu, sum1, 1);
        sum1 += __shfl_xor_sync(0xffffffffu, sum1, 2);
        l_[0] = l_[0] * corr0 + sum0;
        l_[1] = l_[1] * corr1 + sum1;
        m_[0] = mn0; m_[1] = mn1;

#pragma unroll
        for (int nt = 0; nt < 16; nt++) {
            accO[nt][0] *= corr0; accO[nt][1] *= corr0;
            accO[nt][2] *= corr1; accO[nt][3] *= corr1;
        }

        // ---- O += P @ V (bf16x3), warp tile 16x128, k=64 ----
#pragma unroll
        for (int kc = 0; kc < 4; kc++) {
            float p00 = accS[2 * kc][0],     p01 = accS[2 * kc][1];
            float p10 = accS[2 * kc][2],     p11 = accS[2 * kc][3];
            float p20 = accS[2 * kc + 1][0], p21 = accS[2 * kc + 1][1];
            float p30 = accS[2 * kc + 1][2], p31 = accS[2 * kc + 1][3];
            float h00 = __bfloat162float(__float2bfloat16(p00));
            float h01 = __bfloat162float(__float2bfloat16(p01));
            float h10 = __bfloat162float(__float2bfloat16(p10));
            float h11 = __bfloat162float(__float2bfloat16(p11));
            float h20 = __bfloat162float(__float2bfloat16(p20));
            float h21 = __bfloat162float(__float2bfloat16(p21));
            float h30 = __bfloat162float(__float2bfloat16(p30));
            float h31 = __bfloat162float(__float2bfloat16(p31));
            uint32_t ph0 = pack_bf16x2(h00, h01);
            uint32_t ph1 = pack_bf16x2(h10, h11);
            uint32_t ph2 = pack_bf16x2(h20, h21);
            uint32_t ph3 = pack_bf16x2(h30, h31);
            uint32_t pl0 = pack_bf16x2(p00 - h00, p01 - h01);
            uint32_t pl1 = pack_bf16x2(p10 - h10, p11 - h11);
            uint32_t pl2 = pack_bf16x2(p20 - h20, p21 - h21);
            uint32_t pl3 = pack_bf16x2(p30 - h30, p31 - h31);

#pragma unroll
            for (int ncg = 0; ncg < 8; ncg++) {
                uint32_t base_off = (uint32_t)(kc * 16 * 272 + ncg * 32) + vlane_off;
                uint32_t vh0, vh1, vh2, vh3, vl0, vl1, vl2, vl3;
                ldsm_x4_t(vh0, vh1, vh2, vh3, svh + base_off);
                ldsm_x4_t(vl0, vl1, vl2, vl3, svl + base_off);
                mma16816(accO[ncg * 2],     ph0, ph1, ph2, ph3, vh0, vh1);
                mma16816(accO[ncg * 2],     ph0, ph1, ph2, ph3, vl0, vl1);
                mma16816(accO[ncg * 2],     pl0, pl1, pl2, pl3, vh0, vh1);
                mma16816(accO[ncg * 2 + 1], ph0, ph1, ph2, ph3, vh2, vh3);
                mma16816(accO[ncg * 2 + 1], ph0, ph1, ph2, ph3, vl2, vl3);
                mma16816(accO[ncg * 2 + 1], pl0, pl1, pl2, pl3, vh2, vh3);
            }
        }
    }

    // ---- normalize + split-write fp16 hi/lo ----
    float i0 = 1.f / l_[0];
    float i1 = 1.f / l_[1];
#pragma unroll
    for (int nt = 0; nt < 16; nt++) {
        int col = h * DH + nt * 8 + 2 * tg;
        float v0 = accO[nt][0] * i0, v1 = accO[nt][1] * i0;
        float v2 = accO[nt][2] * i1, v3 = accO[nt][3] * i1;
        size_t o0 = (size_t)row0 * HID + col;
        size_t o1 = (size_t)(row0 + 8) * HID + col;
        split2h_store(v0, v1, oh + o0, ol + o0);
        split2h_store(v2, v3, oh + o1, ol + o1);
    }
}

// ---------------------------------------------------------------------------
// Launch
// ---------------------------------------------------------------------------
extern "C" void kernel_launch(void* const* d_in, const int* in_sizes, int n_in,
                              void* d_out, int out_size)
{
    const int*   positions = (const int*)d_in[0];
    const float* hidden    = (const float*)d_in[1];
    const float* w_qkv     = (const float*)d_in[2];
    const float* w_o       = (const float*)d_in[3];
    const float* q_norm_w  = (const float*)d_in[4];
    const float* k_norm_w  = (const float*)d_in[5];
    float*       out       = (float*)d_out;

    __half *ah, *al, *bh;
    __nv_bfloat16 *qsh, *qsl, *ksh, *ksl, *vsh, *vsl;
    float2* rope;
    cudaGetSymbolAddress((void**)&ah, g_ah);
    cudaGetSymbolAddress((void**)&al, g_al);
    cudaGetSymbolAddress((void**)&bh, g_bh);
    cudaGetSymbolAddress((void**)&qsh, g_qsh);
    cudaGetSymbolAddress((void**)&qsl, g_qsl);
    cudaGetSymbolAddress((void**)&ksh, g_ksh);
    cudaGetSymbolAddress((void**)&ksl, g_ksl);
    cudaGetSymbolAddress((void**)&vsh, g_vsh);
    cudaGetSymbolAddress((void**)&vsl, g_vsl);
    cudaGetSymbolAddress((void**)&rope, g_rope);

    cudaFuncSetAttribute(gemm_mma_kernel_t<true>,
                         cudaFuncAttributeMaxDynamicSharedMemorySize, GEMM_SMEM);
    cudaFuncSetAttribute(gemm_mma_kernel_t<false>,
                         cudaFuncAttributeMaxDynamicSharedMemorySize, GEMM_SMEM);
    cudaFuncSetAttribute(attn_kernel,
                         cudaFuncAttributeMaxDynamicSharedMemorySize, ATTN_SMEM);

    // 1. Split hidden to fp16 hi/lo (+ RoPE table); transpose w_qkv to fp16.
    {
        int n = TT * HID;
        split_kernel<<<n / 4 / 256, 256>>>(hidden, ah, al, n, positions, rope);
        dim3 tg(QKVW / 32, HID / 32);
        transpose_half_kernel<<<tg, dim3(32, 8)>>>(w_qkv, bh, HID, QKVW);
    }

    // 2. QKV projection (fp16x2) with FUSED norm/rope/bf16-split epilogue.
    {
        dim3 grid(QKVW / 128, TT / 128);
        gemm_mma_kernel_t<true><<<grid, 256, GEMM_SMEM>>>(
            TT, QKVW, HID, ah, al, bh,
            nullptr, rope, q_norm_w, k_norm_w,
            qsh, qsl, ksh, ksl, vsh, vsl);
    }

    // 3. Causal GQA flash attention (bf16x3); writes fp16 hi/lo into ah/al.
    {
        dim3 grid(NH, TT / AT_BM);
        attn_kernel<<<grid, 256, ATTN_SMEM>>>(
            qsh, qsl, ksh, ksl, vsh, vsl, ah, al);
    }

    // 4. transpose w_o to fp16 (bh free after QKV GEMM).
    {
        dim3 tg(HID / 32, (NH * DH) / 32);
        transpose_half_kernel<<<tg, dim3(32, 8)>>>(w_o, bh, NH * DH, HID);
    }

    // 5. Output projection (fp16x2, plain fp32 epilogue).
    {
        dim3 grid(HID / 128, TT / 128);
        gemm_mma_kernel_t<false><<<grid, 256, GEMM_SMEM>>>(
            TT, HID, NH * DH, ah, al, bh,
            out, nullptr, nullptr, nullptr,
            nullptr, nullptr, nullptr, nullptr, nullptr, nullptr);
    }
}

// round 16
// speedup vs baseline: 1.3983x; 1.1019x over previous
#include <cuda_runtime.h>
#include <cuda_bf16.h>
#include <cuda_fp16.h>
#include <math.h>
#include <math_constants.h>
#include <stdint.h>

// Problem constants
#define TT   2048
#define HID  2048
#define NH   16
#define NKV  8
#define DH   128
#define QKVW ((NH + 2 * NKV) * DH)   // 4096
#define QW   (NH * DH)               // 2048
#define KVW  (NKV * DH)              // 1024
#define EPS  1e-6f

// Scratch (allocation-free rule: __device__ globals)
__device__ __half g_ah[(size_t)TT * HID];            // GEMM A hi (fp16) / attn-out hi
__device__ __half g_al[(size_t)TT * HID];            // GEMM A lo (fp16) / attn-out lo
__device__ __half g_bh[(size_t)QKVW * HID];          // B^T single fp16 ([N,K])
__device__ __half g_qsh[(size_t)TT * QW],  g_qsl[(size_t)TT * QW];  // split Q (scaled, fp16)
__device__ __half g_ksh[(size_t)TT * KVW];           // K single fp16
__device__ __half g_vsh[(size_t)TT * KVW];           // V single fp16
__device__ float2 g_rope[(size_t)TT * 64];           // (cos, sin) per (t, d)

// ---------------------------------------------------------------------------
// PTX helpers (base sm_103 target — HMMA mma.sync + ldmatrix + cp.async)
// ---------------------------------------------------------------------------
__device__ __forceinline__ void mma16816h(float d[4],
                                          uint32_t a0, uint32_t a1, uint32_t a2, uint32_t a3,
                                          uint32_t b0, uint32_t b1)
{
    asm volatile(
        "mma.sync.aligned.m16n8k16.row.col.f32.f16.f16.f32 "
        "{%0,%1,%2,%3}, {%4,%5,%6,%7}, {%8,%9}, {%0,%1,%2,%3};\n"
        : "+f"(d[0]), "+f"(d[1]), "+f"(d[2]), "+f"(d[3])
        : "r"(a0), "r"(a1), "r"(a2), "r"(a3), "r"(b0), "r"(b1));
}

__device__ __forceinline__ void ldsm_x4(uint32_t& r0, uint32_t& r1,
                                        uint32_t& r2, uint32_t& r3, uint32_t addr)
{
    asm volatile("ldmatrix.sync.aligned.m8n8.x4.shared.b16 {%0,%1,%2,%3}, [%4];"
                 : "=r"(r0), "=r"(r1), "=r"(r2), "=r"(r3) : "r"(addr));
}

__device__ __forceinline__ void ldsm_x4_t(uint32_t& r0, uint32_t& r1,
                                          uint32_t& r2, uint32_t& r3, uint32_t addr)
{
    asm volatile("ldmatrix.sync.aligned.m8n8.x4.trans.shared.b16 {%0,%1,%2,%3}, [%4];"
                 : "=r"(r0), "=r"(r1), "=r"(r2), "=r"(r3) : "r"(addr));
}

__device__ __forceinline__ uint32_t su32(const void* p) {
    return (uint32_t)__cvta_generic_to_shared(p);
}

__device__ __forceinline__ uint32_t pack_h2(float a, float b) {
    __half2 t = __floats2half2_rn(a, b);
    return *(uint32_t*)&t;
}

__device__ __forceinline__ void cp_async16(uint32_t dst, const void* src) {
    asm volatile("cp.async.cg.shared.global [%0], [%1], 16;" :: "r"(dst), "l"(src));
}
__device__ __forceinline__ void cp_commit() {
    asm volatile("cp.async.commit_group;" ::: "memory");
}
template <int N>
__device__ __forceinline__ void cp_wait() {
    asm volatile("cp.async.wait_group %0;" :: "n"(N) : "memory");
}

// fp16 hi/lo split of 2 floats -> two u32 stores
__device__ __forceinline__ void split2h_store(float a, float b,
                                              __half* hp, __half* lp) {
    float ha = __half2float(__float2half_rn(a));
    float hb = __half2float(__float2half_rn(b));
    *(uint32_t*)hp = pack_h2(ha, hb);
    *(uint32_t*)lp = pack_h2(a - ha, b - hb);
}

// ---------------------------------------------------------------------------
// Split conversion fp32 -> fp16 hi/lo (+ RoPE table build).
// ---------------------------------------------------------------------------
__global__ __launch_bounds__(256) void split_kernel(
    const float* __restrict__ x,
    __half* __restrict__ hi, __half* __restrict__ lo, int n,
    const int* __restrict__ positions, float2* __restrict__ rope)
{
    int j = blockIdx.x * blockDim.x + threadIdx.x;
    if (rope && j < TT * 64) {
        int t = j >> 6;
        int d = j & 63;
        float pos = (float)positions[t];
        float inv_freq = powf(10000.f, -(float)d * (1.f / 64.f));
        float sv, cv;
        sincosf(pos * inv_freq, &sv, &cv);
        rope[j] = make_float2(cv, sv);
    }
    int i = j * 4;
    if (i >= n) return;
    float4 v = *(const float4*)(x + i);
    split2h_store(v.x, v.y, hi + i, lo + i);
    split2h_store(v.z, v.w, hi + i + 2, lo + i + 2);
}

// ---------------------------------------------------------------------------
// Transpose to single fp16: W[K,N] fp32 -> Th [N,K] fp16. K,N % 32 == 0.
// ---------------------------------------------------------------------------
__global__ __launch_bounds__(256) void transpose_half_kernel(
    const float* __restrict__ W,
    __half* __restrict__ Th, int K, int N)
{
    __shared__ float tile[32][33];
    const int bn = blockIdx.x * 32;
    const int bk = blockIdx.y * 32;
    const int tx = threadIdx.x;
    const int ty = threadIdx.y;
#pragma unroll
    for (int j = 0; j < 32; j += 8)
        tile[ty + j][tx] = W[(size_t)(bk + ty + j) * N + bn + tx];
    __syncthreads();
#pragma unroll
    for (int j = 0; j < 32; j += 8) {
        Th[(size_t)(bn + ty + j) * K + bk + tx] = __float2half_rn(tile[tx][ty + j]);
    }
}

// ---------------------------------------------------------------------------
// mma.sync fp16x2 GEMM: C = A @ B with A = Ah+Al (fp16), B = Bh (fp16).
// 2 MMAs per step. cp.async double-buffered (prefetch-early), ldmatrix frags,
// dynamic smem, 2 CTAs/SM.
// FUSED=true: QKV projection with RMSNorm+RoPE(table)+fp16-split epilogue
// (Q hi/lo; K,V single fp16).
// ---------------------------------------------------------------------------
#define GST   10240   // bytes per stage per array (128 rows x 80B)
#define GARR  20480   // bytes per array (2 stages)
#define GEMM_SMEM 69632

template<bool FUSED>
__global__ __launch_bounds__(256, 2) void gemm_mma_kernel_t(
    int M, int N, int K,
    const __half* __restrict__ Ah, const __half* __restrict__ Al,
    const __half* __restrict__ Bh,
    float* __restrict__ C,
    const float2* __restrict__ rope,
    const float* __restrict__ qw, const float* __restrict__ kw,
    __half* __restrict__ qsh, __half* __restrict__ qsl,
    __half* __restrict__ ksh, __half* __restrict__ vsh)
{
    extern __shared__ __align__(16) char blob[];

    const int tid  = threadIdx.x;
    const int lane = tid & 31;
    const int wid  = tid >> 5;
    const int wm   = wid >> 2;
    const int wn   = wid & 3;
    const int gq   = lane >> 2;
    const int tg   = lane & 3;
    const int bm = blockIdx.y * 128;
    const int bn = blockIdx.x * 128;

    const uint32_t ub = su32(blob);
    const uint32_t a_off = (uint32_t)((lane & 15) * 80 + (lane & 16));
    const uint32_t b_off = (uint32_t)(((lane & 7) + ((lane >> 4) << 3)) * 80 + (((lane >> 3) & 1) << 4));

    float acc[4][4][4];
#pragma unroll
    for (int a = 0; a < 4; a++)
#pragma unroll
        for (int b = 0; b < 4; b++)
#pragma unroll
            for (int c = 0; c < 4; c++) acc[a][b][c] = 0.f;

    const int nch = K / 32;

    auto load_chunk = [&](int c, int st) {
        const int k0 = c * 32;
        const uint32_t sb = ub + (uint32_t)st * GST;
#pragma unroll
        for (int i = 0; i < 2; i++) {
            int u = tid + i * 256;
            int row = u >> 2;
            int q   = u & 3;
            uint32_t so = (uint32_t)(row * 80 + q * 16);
            size_t goA = (size_t)(bm + row) * K + k0 + q * 8;
            size_t goB = (size_t)(bn + row) * K + k0 + q * 8;
            cp_async16(sb + so,             Ah + goA);
            cp_async16(sb + GARR + so,      Al + goA);
            cp_async16(sb + 2 * GARR + so,  Bh + goB);
        }
    };

    load_chunk(0, 0);
    cp_commit();

    for (int c = 0; c < nch; c++) {
        const int st = c & 1;
        if (c + 1 < nch) {
            load_chunk(c + 1, st ^ 1);   // issue early: overlaps wait below
            cp_commit();
            cp_wait<1>();
        } else {
            cp_wait<0>();
        }
        __syncthreads();

        const uint32_t sb = ub + (uint32_t)st * GST;
#pragma unroll
        for (int ks = 0; ks < 2; ks++) {
            const uint32_t kb = (uint32_t)(ks * 32);
            uint32_t ah[4][4], al[4][4], bh[4][2];
#pragma unroll
            for (int mt = 0; mt < 4; mt++) {
                uint32_t base = (uint32_t)((wm * 64 + mt * 16) * 80) + kb + a_off;
                ldsm_x4(ah[mt][0], ah[mt][1], ah[mt][2], ah[mt][3], sb + base);
                ldsm_x4(al[mt][0], al[mt][1], al[mt][2], al[mt][3], sb + GARR + base);
            }
#pragma unroll
            for (int ntp = 0; ntp < 2; ntp++) {
                uint32_t base = (uint32_t)((wn * 32 + ntp * 16) * 80) + kb + b_off;
                ldsm_x4(bh[2 * ntp][0], bh[2 * ntp][1], bh[2 * ntp + 1][0], bh[2 * ntp + 1][1],
                        sb + 2 * GARR + base);
            }
#pragma unroll
            for (int mt = 0; mt < 4; mt++)
#pragma unroll
                for (int nt = 0; nt < 4; nt++) {
                    mma16816h(acc[mt][nt], ah[mt][0], ah[mt][1], ah[mt][2], ah[mt][3],
                              bh[nt][0], bh[nt][1]);
                    mma16816h(acc[mt][nt], al[mt][0], al[mt][1], al[mt][2], al[mt][3],
                              bh[nt][0], bh[nt][1]);
                }
        }
        __syncthreads();
    }

    if constexpr (!FUSED) {
#pragma unroll
        for (int mt = 0; mt < 4; mt++) {
            int row = bm + wm * 64 + mt * 16 + gq;
#pragma unroll
            for (int nt = 0; nt < 4; nt++) {
                int col = bn + wn * 32 + nt * 8 + 2 * tg;
                *(float2*)(C + (size_t)row * N + col) =
                    make_float2(acc[mt][nt][0], acc[mt][nt][1]);
                *(float2*)(C + (size_t)(row + 8) * N + col) =
                    make_float2(acc[mt][nt][2], acc[mt][nt][3]);
            }
        }
        return;
    } else {
        const int slot = bn >> 7;   // head slot 0..31 (0-15 q, 16-23 k, 24-31 v)

        if (slot >= 24) {
            const int vh = slot - 24;
#pragma unroll
            for (int mt = 0; mt < 4; mt++) {
#pragma unroll
                for (int hhalf = 0; hhalf < 2; hhalf++) {
                    int r = wm * 64 + mt * 16 + gq + 8 * hhalf;
                    int t = bm + r;
#pragma unroll
                    for (int nt = 0; nt < 4; nt++) {
                        int cn = wn * 32 + nt * 8 + 2 * tg;
                        size_t o = (size_t)t * KVW + vh * DH + cn;
                        *(uint32_t*)(vsh + o) =
                            pack_h2(acc[mt][nt][2 * hhalf], acc[mt][nt][2 * hhalf + 1]);
                    }
                }
            }
            return;
        }

        // Q/K: RMSNorm + RoPE(table) + fp16 write (Q split hi/lo, K single)
        float* xs   = (float*)blob;              // [128][132] fp32 (67584 B)
        float* sums = (float*)(blob + 67584);    // [128][4]

#pragma unroll
        for (int mt = 0; mt < 4; mt++) {
#pragma unroll
            for (int hhalf = 0; hhalf < 2; hhalf++) {
                float p = 0.f;
#pragma unroll
                for (int nt = 0; nt < 4; nt++) {
                    float v0 = acc[mt][nt][2 * hhalf];
                    float v1 = acc[mt][nt][2 * hhalf + 1];
                    p += v0 * v0 + v1 * v1;
                }
                p += __shfl_xor_sync(0xffffffffu, p, 1);
                p += __shfl_xor_sync(0xffffffffu, p, 2);
                if (tg == 0) {
                    int r = wm * 64 + mt * 16 + gq + 8 * hhalf;
                    sums[r * 4 + wn] = p;
                }
            }
        }
        __syncthreads();

        const float* wvec = (slot < NH) ? qw : kw;
        float wcol[8];
#pragma unroll
        for (int nt = 0; nt < 4; nt++) {
            int cn = wn * 32 + nt * 8 + 2 * tg;
            wcol[2 * nt]     = wvec[cn];
            wcol[2 * nt + 1] = wvec[cn + 1];
        }
#pragma unroll
        for (int mt = 0; mt < 4; mt++) {
#pragma unroll
            for (int hhalf = 0; hhalf < 2; hhalf++) {
                int r = wm * 64 + mt * 16 + gq + 8 * hhalf;
                float ssum = sums[r * 4 + 0] + sums[r * 4 + 1] + sums[r * 4 + 2] + sums[r * 4 + 3];
                float rinv = rsqrtf(ssum * (1.f / DH) + EPS);
#pragma unroll
                for (int nt = 0; nt < 4; nt++) {
                    int cn = wn * 32 + nt * 8 + 2 * tg;
                    xs[r * 132 + cn]     = acc[mt][nt][2 * hhalf] * rinv * wcol[2 * nt];
                    xs[r * 132 + cn + 1] = acc[mt][nt][2 * hhalf + 1] * rinv * wcol[2 * nt + 1];
                }
            }
        }
        __syncthreads();

        const bool isq = (slot < NH);
        const float qscale = 0.08838834764831845f;   // 1/sqrt(128)
#pragma unroll
        for (int mt = 0; mt < 4; mt++) {
#pragma unroll
            for (int hhalf = 0; hhalf < 2; hhalf++) {
                int r = wm * 64 + mt * 16 + gq + 8 * hhalf;
                int t = bm + r;
#pragma unroll
                for (int nt = 0; nt < 4; nt++) {
                    int cn = wn * 32 + nt * 8 + 2 * tg;
                    int d  = cn & 63;
                    float x0 = xs[r * 132 + cn];
                    float x1 = xs[r * 132 + cn + 1];
                    float p0 = xs[r * 132 + (cn ^ 64)];
                    float p1 = xs[r * 132 + (cn ^ 64) + 1];
                    float2 cs0 = rope[t * 64 + d];
                    float2 cs1 = rope[t * 64 + d + 1];
                    float o0, o1;
                    if (cn < 64) {
                        o0 = x0 * cs0.x - p0 * cs0.y;
                        o1 = x1 * cs1.x - p1 * cs1.y;
                    } else {
                        o0 = x0 * cs0.x + p0 * cs0.y;
                        o1 = x1 * cs1.x + p1 * cs1.y;
                    }
                    if (isq) {
                        o0 *= qscale; o1 *= qscale;
                        size_t o = (size_t)t * QW + slot * DH + cn;
                        split2h_store(o0, o1, qsh + o, qsl + o);
                    } else {
                        size_t o = (size_t)t * KVW + (slot - NH) * DH + cn;
                        *(uint32_t*)(ksh + o) = pack_h2(o0, o1);
                    }
                }
            }
        }
    }
}

// ---------------------------------------------------------------------------
// FA2-style causal GQA attention, fp16x2 mma, in-register softmax.
// K,V single fp16; Q,P split fp16 hi/lo. 3-stage cp.async pipeline.
// Epilogue writes fp16 hi/lo (feeds the fp16x2 O-projection).
// ---------------------------------------------------------------------------
#define AT_BM 128
#define AT_BN 64
#define AT_ARR   17408    // bytes per 64-row array (64 rows x 272B)
#define AT_STG   34816    // bytes per stage (K, V)
#define AT_QOFF  (3 * AT_STG)              // Q hi at 104448, lo at +34816
#define ATTN_SMEM (3 * AT_STG + 4 * AT_ARR)   // 104448 + 69632 = 174080

__global__ __launch_bounds__(256, 1) void attn_kernel(
    const __half* __restrict__ qsh, const __half* __restrict__ qsl,
    const __half* __restrict__ ksh, const __half* __restrict__ vsh,
    __half* __restrict__ oh, __half* __restrict__ ol)
{
    extern __shared__ __align__(16) char asmem[];

    const int h   = blockIdx.x;
    const int m0  = (gridDim.y - 1 - blockIdx.y) * AT_BM;  // heavy blocks first
    const int kvh = h >> 1;
    const int tid = threadIdx.x;
    const int lane = tid & 31;
    const int w    = tid >> 5;
    const int gq   = lane >> 2;
    const int tg   = lane & 3;

    const uint32_t ub = su32(asmem);
    const uint32_t uS[3] = { ub, ub + AT_STG, ub + 2 * AT_STG };
    const uint32_t uQ = ub + AT_QOFF;

    const uint32_t a_off = (uint32_t)((lane & 15) * 272 + (lane & 16));
    const uint32_t b_off = (uint32_t)(((lane & 7) + ((lane >> 4) << 3)) * 272 + (((lane >> 3) & 1) << 4));
    const uint32_t vlane_off = (uint32_t)((lane & 15) * 272 + ((lane >> 4) << 4));

    auto prefetch = [&](int n0, int st) {
        const uint32_t sb = uS[st];
#pragma unroll
        for (int i = 0; i < 4; i++) {
            int u = tid + i * 256;
            int row = u >> 4;
            int c   = u & 15;
            uint32_t so = (uint32_t)(row * 272 + c * 16);
            size_t go = (size_t)(n0 + row) * KVW + kvh * DH + c * 8;
            cp_async16(sb + so,          ksh + go);
            cp_async16(sb + AT_ARR + so, vsh + go);
        }
    };

    const int n_tiles = (m0 + AT_BM) / AT_BN;   // >= 2 always

    prefetch(0, 0);
    cp_commit();
    prefetch(AT_BN, 1);
    cp_commit();

    // Q tile -> smem (plain stores), then hoist to registers
    for (int u = tid; u < AT_BM * 16; u += 256) {
        int row = u >> 4;
        int c   = u & 15;
        size_t go = (size_t)(m0 + row) * QW + h * DH + c * 8;
        uint32_t so = (uint32_t)(row * 272 + c * 16);
        *(uint4*)(asmem + AT_QOFF + so)         = *(const uint4*)(qsh + go);
        *(uint4*)(asmem + AT_QOFF + 34816 + so) = *(const uint4*)(qsl + go);
    }
    __syncthreads();

    uint32_t qfh[8][4], qfl[8][4];
#pragma unroll
    for (int ks = 0; ks < 8; ks++) {
        uint32_t qbase = (uint32_t)(w * 16 * 272 + ks * 32) + a_off;
        ldsm_x4(qfh[ks][0], qfh[ks][1], qfh[ks][2], qfh[ks][3], uQ + qbase);
        ldsm_x4(qfl[ks][0], qfl[ks][1], qfl[ks][2], qfl[ks][3], uQ + 34816 + qbase);
    }

    float m_[2] = { -CUDART_INF_F, -CUDART_INF_F };
    float l_[2] = { 0.f, 0.f };

    float accO[16][4];
#pragma unroll
    for (int a = 0; a < 16; a++)
#pragma unroll
        for (int c = 0; c < 4; c++) accO[a][c] = 0.f;

    const int row0 = m0 + w * 16 + gq;

    for (int tile = 0; tile < n_tiles; tile++) {
        const int n0 = tile * AT_BN;
        const int st = tile % 3;

        if (tile + 2 <= n_tiles) cp_wait<1>();
        else                     cp_wait<0>();
        __syncthreads();

        if (tile + 2 < n_tiles) {
            prefetch(n0 + 2 * AT_BN, (tile + 2) % 3);
            cp_commit();
        }

        const uint32_t kh = uS[st];
        const uint32_t sv = uS[st] + AT_ARR;

        // ---- S = Q @ K^T (fp16x2), warp tile 16x64 ----
        float accS[8][4];
#pragma unroll
        for (int bb = 0; bb < 8; bb++)
#pragma unroll
            for (int c = 0; c < 4; c++) accS[bb][c] = 0.f;

#pragma unroll
        for (int ks = 0; ks < 8; ks++) {
            const uint32_t kb = (uint32_t)(ks * 32);
#pragma unroll
            for (int ntp = 0; ntp < 4; ntp++) {
                uint32_t base = (uint32_t)(ntp * 16 * 272) + kb + b_off;
                uint32_t bh0, bh1, bh2, bh3;
                ldsm_x4(bh0, bh1, bh2, bh3, kh + base);
                mma16816h(accS[2 * ntp],     qfh[ks][0], qfh[ks][1], qfh[ks][2], qfh[ks][3], bh0, bh1);
                mma16816h(accS[2 * ntp],     qfl[ks][0], qfl[ks][1], qfl[ks][2], qfl[ks][3], bh0, bh1);
                mma16816h(accS[2 * ntp + 1], qfh[ks][0], qfh[ks][1], qfh[ks][2], qfh[ks][3], bh2, bh3);
                mma16816h(accS[2 * ntp + 1], qfl[ks][0], qfl[ks][1], qfl[ks][2], qfl[ks][3], bh2, bh3);
            }
        }

        // ---- causal mask ----
        if (n0 + AT_BN - 1 > m0) {
#pragma unroll
            for (int nt = 0; nt < 8; nt++) {
                int c0 = n0 + nt * 8 + 2 * tg;
                if (c0     > row0)     accS[nt][0] = -CUDART_INF_F;
                if (c0 + 1 > row0)     accS[nt][1] = -CUDART_INF_F;
                if (c0     > row0 + 8) accS[nt][2] = -CUDART_INF_F;
                if (c0 + 1 > row0 + 8) accS[nt][3] = -CUDART_INF_F;
            }
        }

        // ---- in-register online softmax ----
        float mx0 = accS[0][0], mx1 = accS[0][2];
#pragma unroll
        for (int nt = 0; nt < 8; nt++) {
            mx0 = fmaxf(mx0, fmaxf(accS[nt][0], accS[nt][1]));
            mx1 = fmaxf(mx1, fmaxf(accS[nt][2], accS[nt][3]));
        }
        mx0 = fmaxf(mx0, __shfl_xor_sync(0xffffffffu, mx0, 1));
        mx0 = fmaxf(mx0, __shfl_xor_sync(0xffffffffu, mx0, 2));
        mx1 = fmaxf(mx1, __shfl_xor_sync(0xffffffffu, mx1, 1));
        mx1 = fmaxf(mx1, __shfl_xor_sync(0xffffffffu, mx1, 2));

        float mn0 = fmaxf(m_[0], mx0);
        float mn1 = fmaxf(m_[1], mx1);
        float corr0 = __expf(m_[0] - mn0);
        float corr1 = __expf(m_[1] - mn1);
        float sum0 = 0.f, sum1 = 0.f;
#pragma unroll
        for (int nt = 0; nt < 8; nt++) {
            accS[nt][0] = __expf(accS[nt][0] - mn0);
            accS[nt][1] = __expf(accS[nt][1] - mn0);
            accS[nt][2] = __expf(accS[nt][2] - mn1);
            accS[nt][3] = __expf(accS[nt][3] - mn1);
            sum0 += accS[nt][0] + accS[nt][1];
            sum1 += accS[nt][2] + accS[nt][3];
        }
        sum0 += __shfl_xor_sync(0xffffffffu, sum0, 1);
        sum0 += __shfl_xor_sync(0xffffffffu, sum0, 2);
        sum1 += __shfl_xor_sync(0xffffffffu, sum1, 1);
        sum1 += __shfl_xor_sync(0xffffffffu, sum1, 2);
        l_[0] = l_[0] * corr0 + sum0;
        l_[1] = l_[1] * corr1 + sum1;
        m_[0] = mn0; m_[1] = mn1;

#pragma unroll
        for (int nt = 0; nt < 16; nt++) {
            accO[nt][0] *= corr0; accO[nt][1] *= corr0;
            accO[nt][2] *= corr1; accO[nt][3] *= corr1;
        }

        // ---- O += P @ V (fp16x2), warp tile 16x128, k=64 ----
#pragma unroll
        for (int kc = 0; kc < 4; kc++) {
            float p00 = accS[2 * kc][0],     p01 = accS[2 * kc][1];
            float p10 = accS[2 * kc][2],     p11 = accS[2 * kc][3];
            float p20 = accS[2 * kc + 1][0], p21 = accS[2 * kc + 1][1];
            float p30 = accS[2 * kc + 1][2], p31 = accS[2 * kc + 1][3];
            float h00 = __half2float(__float2half_rn(p00));
            float h01 = __half2float(__float2half_rn(p01));
            float h10 = __half2float(__float2half_rn(p10));
            float h11 = __half2float(__float2half_rn(p11));
            float h20 = __half2float(__float2half_rn(p20));
            float h21 = __half2float(__float2half_rn(p21));
            float h30 = __half2float(__float2half_rn(p30));
            float h31 = __half2float(__float2half_rn(p31));
            uint32_t ph0 = pack_h2(h00, h01);
            uint32_t ph1 = pack_h2(h10, h11);
            uint32_t ph2 = pack_h2(h20, h21);
            uint32_t ph3 = pack_h2(h30, h31);
            uint32_t pl0 = pack_h2(p00 - h00, p01 - h01);
            uint32_t pl1 = pack_h2(p10 - h10, p11 - h11);
            uint32_t pl2 = pack_h2(p20 - h20, p21 - h21);
            uint32_t pl3 = pack_h2(p30 - h30, p31 - h31);

#pragma unroll
            for (int ncg = 0; ncg < 8; ncg++) {
                uint32_t base_off = (uint32_t)(kc * 16 * 272 + ncg * 32) + vlane_off;
                uint32_t v0, v1, v2, v3;
                ldsm_x4_t(v0, v1, v2, v3, sv + base_off);
                mma16816h(accO[ncg * 2],     ph0, ph1, ph2, ph3, v0, v1);
                mma16816h(accO[ncg * 2],     pl0, pl1, pl2, pl3, v0, v1);
                mma16816h(accO[ncg * 2 + 1], ph0, ph1, ph2, ph3, v2, v3);
                mma16816h(accO[ncg * 2 + 1], pl0, pl1, pl2, pl3, v2, v3);
            }
        }
    }

    // ---- normalize + split-write fp16 hi/lo ----
    float i0 = 1.f / l_[0];
    float i1 = 1.f / l_[1];
#pragma unroll
    for (int nt = 0; nt < 16; nt++) {
        int col = h * DH + nt * 8 + 2 * tg;
        float v0 = accO[nt][0] * i0, v1 = accO[nt][1] * i0;
        float v2 = accO[nt][2] * i1, v3 = accO[nt][3] * i1;
        size_t o0 = (size_t)row0 * HID + col;
        size_t o1 = (size_t)(row0 + 8) * HID + col;
        split2h_store(v0, v1, oh + o0, ol + o0);
        split2h_store(v2, v3, oh + o1, ol + o1);
    }
}

// ---------------------------------------------------------------------------
// Launch
// ---------------------------------------------------------------------------
extern "C" void kernel_launch(void* const* d_in, const int* in_sizes, int n_in,
                              void* d_out, int out_size)
{
    const int*   positions = (const int*)d_in[0];
    const float* hidden    = (const float*)d_in[1];
    const float* w_qkv     = (const float*)d_in[2];
    const float* w_o       = (const float*)d_in[3];
    const float* q_norm_w  = (const float*)d_in[4];
    const float* k_norm_w  = (const float*)d_in[5];
    float*       out       = (float*)d_out;

    __half *ah, *al, *bh, *qsh, *qsl, *ksh, *vsh;
    float2* rope;
    cudaGetSymbolAddress((void**)&ah, g_ah);
    cudaGetSymbolAddress((void**)&al, g_al);
    cudaGetSymbolAddress((void**)&bh, g_bh);
    cudaGetSymbolAddress((void**)&qsh, g_qsh);
    cudaGetSymbolAddress((void**)&qsl, g_qsl);
    cudaGetSymbolAddress((void**)&ksh, g_ksh);
    cudaGetSymbolAddress((void**)&vsh, g_vsh);
    cudaGetSymbolAddress((void**)&rope, g_rope);

    cudaFuncSetAttribute(gemm_mma_kernel_t<true>,
                         cudaFuncAttributeMaxDynamicSharedMemorySize, GEMM_SMEM);
    cudaFuncSetAttribute(gemm_mma_kernel_t<false>,
                         cudaFuncAttributeMaxDynamicSharedMemorySize, GEMM_SMEM);
    static_assert(ATTN_SMEM <= 227 * 1024, "attn smem over limit");
    cudaFuncSetAttribute(attn_kernel,
                         cudaFuncAttributeMaxDynamicSharedMemorySize, ATTN_SMEM);

    // 1. Split hidden to fp16 hi/lo (+ RoPE table); transpose w_qkv to fp16.
    {
        int n = TT * HID;
        split_kernel<<<n / 4 / 256, 256>>>(hidden, ah, al, n, positions, rope);
        dim3 tg(QKVW / 32, HID / 32);
        transpose_half_kernel<<<tg, dim3(32, 8)>>>(w_qkv, bh, HID, QKVW);
    }

    // 2. QKV projection (fp16x2) with FUSED norm/rope/split epilogue.
    {
        dim3 grid(QKVW / 128, TT / 128);
        gemm_mma_kernel_t<true><<<grid, 256, GEMM_SMEM>>>(
            TT, QKVW, HID, ah, al, bh,
            nullptr, rope, q_norm_w, k_norm_w,
            qsh, qsl, ksh, vsh);
    }

    // 3. Causal GQA flash attention (fp16x2); writes fp16 hi/lo into ah/al.
    {
        dim3 grid(NH, TT / AT_BM);
        attn_kernel<<<grid, 256, ATTN_SMEM>>>(
            qsh, qsl, ksh, vsh, ah, al);
    }

    // 4. transpose w_o to fp16 (bh free after QKV GEMM).
    {
        dim3 tg(HID / 32, (NH * DH) / 32);
        transpose_half_kernel<<<tg, dim3(32, 8)>>>(w_o, bh, NH * DH, HID);
    }

    // 5. Output projection (fp16x2, plain fp32 epilogue).
    {
        dim3 grid(HID / 128, TT / 128);
        gemm_mma_kernel_t<false><<<grid, 256, GEMM_SMEM>>>(
            TT, HID, NH * DH, ah, al, bh,
            out, nullptr, nullptr, nullptr,
            nullptr, nullptr, nullptr, nullptr);
    }
}

// round 17
// speedup vs baseline: 1.9396x; 1.3871x over previous
#include <cuda_runtime.h>
#include <cuda_bf16.h>
#include <cuda_fp16.h>
#include <math.h>
#include <math_constants.h>
#include <stdint.h>

// Problem constants
#define TT   2048
#define HID  2048
#define NH   16
#define NKV  8
#define DH   128
#define QKVW ((NH + 2 * NKV) * DH)   // 4096
#define QW   (NH * DH)               // 2048
#define KVW  (NKV * DH)              // 1024
#define EPS  1e-6f

// Scratch (allocation-free rule: __device__ globals)
__device__ __half g_ah[(size_t)TT * HID];            // GEMM A (fp16) / attn-out
__device__ __half g_bh[(size_t)QKVW * HID];          // B^T single fp16 ([N,K])
__device__ __half g_qsh[(size_t)TT * QW],  g_qsl[(size_t)TT * QW];  // split Q (scaled, fp16)
__device__ __half g_ksh[(size_t)TT * KVW];           // K single fp16
__device__ __half g_vsh[(size_t)TT * KVW];           // V single fp16
__device__ float2 g_rope[(size_t)TT * 64];           // (cos, sin) per (t, d)

// ---------------------------------------------------------------------------
// PTX helpers (base sm_103 target — HMMA mma.sync + ldmatrix + cp.async)
// ---------------------------------------------------------------------------
__device__ __forceinline__ void mma16816h(float d[4],
                                          uint32_t a0, uint32_t a1, uint32_t a2, uint32_t a3,
                                          uint32_t b0, uint32_t b1)
{
    asm volatile(
        "mma.sync.aligned.m16n8k16.row.col.f32.f16.f16.f32 "
        "{%0,%1,%2,%3}, {%4,%5,%6,%7}, {%8,%9}, {%0,%1,%2,%3};\n"
        : "+f"(d[0]), "+f"(d[1]), "+f"(d[2]), "+f"(d[3])
        : "r"(a0), "r"(a1), "r"(a2), "r"(a3), "r"(b0), "r"(b1));
}

__device__ __forceinline__ void ldsm_x4(uint32_t& r0, uint32_t& r1,
                                        uint32_t& r2, uint32_t& r3, uint32_t addr)
{
    asm volatile("ldmatrix.sync.aligned.m8n8.x4.shared.b16 {%0,%1,%2,%3}, [%4];"
                 : "=r"(r0), "=r"(r1), "=r"(r2), "=r"(r3) : "r"(addr));
}

__device__ __forceinline__ void ldsm_x4_t(uint32_t& r0, uint32_t& r1,
                                          uint32_t& r2, uint32_t& r3, uint32_t addr)
{
    asm volatile("ldmatrix.sync.aligned.m8n8.x4.trans.shared.b16 {%0,%1,%2,%3}, [%4];"
                 : "=r"(r0), "=r"(r1), "=r"(r2), "=r"(r3) : "r"(addr));
}

__device__ __forceinline__ uint32_t su32(const void* p) {
    return (uint32_t)__cvta_generic_to_shared(p);
}

__device__ __forceinline__ uint32_t pack_h2(float a, float b) {
    __half2 t = __floats2half2_rn(a, b);
    return *(uint32_t*)&t;
}

__device__ __forceinline__ void cp_async16(uint32_t dst, const void* src) {
    asm volatile("cp.async.cg.shared.global [%0], [%1], 16;" :: "r"(dst), "l"(src));
}
__device__ __forceinline__ void cp_commit() {
    asm volatile("cp.async.commit_group;" ::: "memory");
}
template <int N>
__device__ __forceinline__ void cp_wait() {
    asm volatile("cp.async.wait_group %0;" :: "n"(N) : "memory");
}

// fp16 hi/lo split of 2 floats -> two u32 stores
__device__ __forceinline__ void split2h_store(float a, float b,
                                              __half* hp, __half* lp) {
    float ha = __half2float(__float2half_rn(a));
    float hb = __half2float(__float2half_rn(b));
    *(uint32_t*)hp = pack_h2(ha, hb);
    *(uint32_t*)lp = pack_h2(a - ha, b - hb);
}

// ---------------------------------------------------------------------------
// Convert fp32 -> fp16 (+ RoPE table build).
// ---------------------------------------------------------------------------
__global__ __launch_bounds__(256) void convert_kernel(
    const float* __restrict__ x,
    __half* __restrict__ hi, int n,
    const int* __restrict__ positions, float2* __restrict__ rope)
{
    int j = blockIdx.x * blockDim.x + threadIdx.x;
    if (rope && j < TT * 64) {
        int t = j >> 6;
        int d = j & 63;
        float pos = (float)positions[t];
        float inv_freq = powf(10000.f, -(float)d * (1.f / 64.f));
        float sv, cv;
        sincosf(pos * inv_freq, &sv, &cv);
        rope[j] = make_float2(cv, sv);
    }
    int i = j * 4;
    if (i >= n) return;
    float4 v = *(const float4*)(x + i);
    *(uint32_t*)(hi + i)     = pack_h2(v.x, v.y);
    *(uint32_t*)(hi + i + 2) = pack_h2(v.z, v.w);
}

// ---------------------------------------------------------------------------
// Transpose to single fp16: W[K,N] fp32 -> Th [N,K] fp16. K,N % 32 == 0.
// ---------------------------------------------------------------------------
__global__ __launch_bounds__(256) void transpose_half_kernel(
    const float* __restrict__ W,
    __half* __restrict__ Th, int K, int N)
{
    __shared__ float tile[32][33];
    const int bn = blockIdx.x * 32;
    const int bk = blockIdx.y * 32;
    const int tx = threadIdx.x;
    const int ty = threadIdx.y;
#pragma unroll
    for (int j = 0; j < 32; j += 8)
        tile[ty + j][tx] = W[(size_t)(bk + ty + j) * N + bn + tx];
    __syncthreads();
#pragma unroll
    for (int j = 0; j < 32; j += 8) {
        Th[(size_t)(bn + ty + j) * K + bk + tx] = __float2half_rn(tile[tx][ty + j]);
    }
}

// ---------------------------------------------------------------------------
// mma.sync fp16 GEMM: C = A @ B, single fp16 A and B, 1 MMA per step.
// cp.async double-buffered (prefetch-early), ldmatrix frags, 2 CTAs/SM.
// FUSED=true: QKV projection with RMSNorm+RoPE(table)+fp16 epilogue
// (Q hi/lo split; K,V single fp16).
// ---------------------------------------------------------------------------
#define GST   10240   // bytes per stage per array (128 rows x 80B)
#define GARR  20480   // bytes per array (2 stages)
#define GEMM_SMEM 69632   // mainloop needs 40960; fused epilogue needs 69632

template<bool FUSED>
__global__ __launch_bounds__(256, 2) void gemm_mma_kernel_t(
    int M, int N, int K,
    const __half* __restrict__ Ah,
    const __half* __restrict__ Bh,
    float* __restrict__ C,
    const float2* __restrict__ rope,
    const float* __restrict__ qw, const float* __restrict__ kw,
    __half* __restrict__ qsh, __half* __restrict__ qsl,
    __half* __restrict__ ksh, __half* __restrict__ vsh)
{
    extern __shared__ __align__(16) char blob[];

    const int tid  = threadIdx.x;
    const int lane = tid & 31;
    const int wid  = tid >> 5;
    const int wm   = wid >> 2;
    const int wn   = wid & 3;
    const int gq   = lane >> 2;
    const int tg   = lane & 3;
    const int bm = blockIdx.y * 128;
    const int bn = blockIdx.x * 128;

    const uint32_t ub = su32(blob);
    const uint32_t a_off = (uint32_t)((lane & 15) * 80 + (lane & 16));
    const uint32_t b_off = (uint32_t)(((lane & 7) + ((lane >> 4) << 3)) * 80 + (((lane >> 3) & 1) << 4));

    float acc[4][4][4];
#pragma unroll
    for (int a = 0; a < 4; a++)
#pragma unroll
        for (int b = 0; b < 4; b++)
#pragma unroll
            for (int c = 0; c < 4; c++) acc[a][b][c] = 0.f;

    const int nch = K / 32;

    auto load_chunk = [&](int c, int st) {
        const int k0 = c * 32;
        const uint32_t sb = ub + (uint32_t)st * GST;
#pragma unroll
        for (int i = 0; i < 2; i++) {
            int u = tid + i * 256;
            int row = u >> 2;
            int q   = u & 3;
            uint32_t so = (uint32_t)(row * 80 + q * 16);
            size_t goA = (size_t)(bm + row) * K + k0 + q * 8;
            size_t goB = (size_t)(bn + row) * K + k0 + q * 8;
            cp_async16(sb + so,        Ah + goA);
            cp_async16(sb + GARR + so, Bh + goB);
        }
    };

    load_chunk(0, 0);
    cp_commit();

    for (int c = 0; c < nch; c++) {
        const int st = c & 1;
        if (c + 1 < nch) {
            load_chunk(c + 1, st ^ 1);   // issue early: overlaps wait below
            cp_commit();
            cp_wait<1>();
        } else {
            cp_wait<0>();
        }
        __syncthreads();

        const uint32_t sb = ub + (uint32_t)st * GST;
#pragma unroll
        for (int ks = 0; ks < 2; ks++) {
            const uint32_t kb = (uint32_t)(ks * 32);
            uint32_t ah[4][4], bh[4][2];
#pragma unroll
            for (int mt = 0; mt < 4; mt++) {
                uint32_t base = (uint32_t)((wm * 64 + mt * 16) * 80) + kb + a_off;
                ldsm_x4(ah[mt][0], ah[mt][1], ah[mt][2], ah[mt][3], sb + base);
            }
#pragma unroll
            for (int ntp = 0; ntp < 2; ntp++) {
                uint32_t base = (uint32_t)((wn * 32 + ntp * 16) * 80) + kb + b_off;
                ldsm_x4(bh[2 * ntp][0], bh[2 * ntp][1], bh[2 * ntp + 1][0], bh[2 * ntp + 1][1],
                        sb + GARR + base);
            }
#pragma unroll
            for (int mt = 0; mt < 4; mt++)
#pragma unroll
                for (int nt = 0; nt < 4; nt++) {
                    mma16816h(acc[mt][nt], ah[mt][0], ah[mt][1], ah[mt][2], ah[mt][3],
                              bh[nt][0], bh[nt][1]);
                }
        }
        __syncthreads();
    }

    if constexpr (!FUSED) {
#pragma unroll
        for (int mt = 0; mt < 4; mt++) {
            int row = bm + wm * 64 + mt * 16 + gq;
#pragma unroll
            for (int nt = 0; nt < 4; nt++) {
                int col = bn + wn * 32 + nt * 8 + 2 * tg;
                *(float2*)(C + (size_t)row * N + col) =
                    make_float2(acc[mt][nt][0], acc[mt][nt][1]);
                *(float2*)(C + (size_t)(row + 8) * N + col) =
                    make_float2(acc[mt][nt][2], acc[mt][nt][3]);
            }
        }
        return;
    } else {
        const int slot = bn >> 7;   // head slot 0..31 (0-15 q, 16-23 k, 24-31 v)

        if (slot >= 24) {
            const int vh = slot - 24;
#pragma unroll
            for (int mt = 0; mt < 4; mt++) {
#pragma unroll
                for (int hhalf = 0; hhalf < 2; hhalf++) {
                    int r = wm * 64 + mt * 16 + gq + 8 * hhalf;
                    int t = bm + r;
#pragma unroll
                    for (int nt = 0; nt < 4; nt++) {
                        int cn = wn * 32 + nt * 8 + 2 * tg;
                        size_t o = (size_t)t * KVW + vh * DH + cn;
                        *(uint32_t*)(vsh + o) =
                            pack_h2(acc[mt][nt][2 * hhalf], acc[mt][nt][2 * hhalf + 1]);
                    }
                }
            }
            return;
        }

        // Q/K: RMSNorm + RoPE(table) + fp16 write (Q split hi/lo, K single)
        float* xs   = (float*)blob;              // [128][132] fp32 (67584 B)
        float* sums = (float*)(blob + 67584);    // [128][4]

#pragma unroll
        for (int mt = 0; mt < 4; mt++) {
#pragma unroll
            for (int hhalf = 0; hhalf < 2; hhalf++) {
                float p = 0.f;
#pragma unroll
                for (int nt = 0; nt < 4; nt++) {
                    float v0 = acc[mt][nt][2 * hhalf];
                    float v1 = acc[mt][nt][2 * hhalf + 1];
                    p += v0 * v0 + v1 * v1;
                }
                p += __shfl_xor_sync(0xffffffffu, p, 1);
                p += __shfl_xor_sync(0xffffffffu, p, 2);
                if (tg == 0) {
                    int r = wm * 64 + mt * 16 + gq + 8 * hhalf;
                    sums[r * 4 + wn] = p;
                }
            }
        }
        __syncthreads();

        const float* wvec = (slot < NH) ? qw : kw;
        float wcol[8];
#pragma unroll
        for (int nt = 0; nt < 4; nt++) {
            int cn = wn * 32 + nt * 8 + 2 * tg;
            wcol[2 * nt]     = wvec[cn];
            wcol[2 * nt + 1] = wvec[cn + 1];
        }
#pragma unroll
        for (int mt = 0; mt < 4; mt++) {
#pragma unroll
            for (int hhalf = 0; hhalf < 2; hhalf++) {
                int r = wm * 64 + mt * 16 + gq + 8 * hhalf;
                float ssum = sums[r * 4 + 0] + sums[r * 4 + 1] + sums[r * 4 + 2] + sums[r * 4 + 3];
                float rinv = rsqrtf(ssum * (1.f / DH) + EPS);
#pragma unroll
                for (int nt = 0; nt < 4; nt++) {
                    int cn = wn * 32 + nt * 8 + 2 * tg;
                    xs[r * 132 + cn]     = acc[mt][nt][2 * hhalf] * rinv * wcol[2 * nt];
                    xs[r * 132 + cn + 1] = acc[mt][nt][2 * hhalf + 1] * rinv * wcol[2 * nt + 1];
                }
            }
        }
        __syncthreads();

        const bool isq = (slot < NH);
        const float qscale = 0.08838834764831845f;   // 1/sqrt(128)
#pragma unroll
        for (int mt = 0; mt < 4; mt++) {
#pragma unroll
            for (int hhalf = 0; hhalf < 2; hhalf++) {
                int r = wm * 64 + mt * 16 + gq + 8 * hhalf;
                int t = bm + r;
#pragma unroll
                for (int nt = 0; nt < 4; nt++) {
                    int cn = wn * 32 + nt * 8 + 2 * tg;
                    int d  = cn & 63;
                    float x0 = xs[r * 132 + cn];
                    float x1 = xs[r * 132 + cn + 1];
                    float p0 = xs[r * 132 + (cn ^ 64)];
                    float p1 = xs[r * 132 + (cn ^ 64) + 1];
                    float2 cs0 = rope[t * 64 + d];
                    float2 cs1 = rope[t * 64 + d + 1];
                    float o0, o1;
                    if (cn < 64) {
                        o0 = x0 * cs0.x - p0 * cs0.y;
                        o1 = x1 * cs1.x - p1 * cs1.y;
                    } else {
                        o0 = x0 * cs0.x + p0 * cs0.y;
                        o1 = x1 * cs1.x + p1 * cs1.y;
                    }
                    if (isq) {
                        o0 *= qscale; o1 *= qscale;
                        size_t o = (size_t)t * QW + slot * DH + cn;
                        split2h_store(o0, o1, qsh + o, qsl + o);
                    } else {
                        size_t o = (size_t)t * KVW + (slot - NH) * DH + cn;
                        *(uint32_t*)(ksh + o) = pack_h2(o0, o1);
                    }
                }
            }
        }
    }
}

// ---------------------------------------------------------------------------
// FA2-style causal GQA attention, fp16x2 mma, in-register softmax.
// K,V single fp16; Q,P split fp16 hi/lo. 3-stage cp.async pipeline.
// Epilogue writes single fp16 (feeds the single-fp16 O-projection).
// ---------------------------------------------------------------------------
#define AT_BM 128
#define AT_BN 64
#define AT_ARR   17408    // bytes per 64-row array (64 rows x 272B)
#define AT_STG   34816    // bytes per stage (K, V)
#define AT_QOFF  (3 * AT_STG)              // Q hi at 104448, lo at +34816
#define ATTN_SMEM (3 * AT_STG + 4 * AT_ARR)   // 174080

__global__ __launch_bounds__(256, 1) void attn_kernel(
    const __half* __restrict__ qsh, const __half* __restrict__ qsl,
    const __half* __restrict__ ksh, const __half* __restrict__ vsh,
    __half* __restrict__ oh)
{
    extern __shared__ __align__(16) char asmem[];

    const int h   = blockIdx.x;
    const int m0  = (gridDim.y - 1 - blockIdx.y) * AT_BM;  // heavy blocks first
    const int kvh = h >> 1;
    const int tid = threadIdx.x;
    const int lane = tid & 31;
    const int w    = tid >> 5;
    const int gq   = lane >> 2;
    const int tg   = lane & 3;

    const uint32_t ub = su32(asmem);
    const uint32_t uS[3] = { ub, ub + AT_STG, ub + 2 * AT_STG };
    const uint32_t uQ = ub + AT_QOFF;

    const uint32_t a_off = (uint32_t)((lane & 15) * 272 + (lane & 16));
    const uint32_t b_off = (uint32_t)(((lane & 7) + ((lane >> 4) << 3)) * 272 + (((lane >> 3) & 1) << 4));
    const uint32_t vlane_off = (uint32_t)((lane & 15) * 272 + ((lane >> 4) << 4));

    auto prefetch = [&](int n0, int st) {
        const uint32_t sb = uS[st];
#pragma unroll
        for (int i = 0; i < 4; i++) {
            int u = tid + i * 256;
            int row = u >> 4;
            int c   = u & 15;
            uint32_t so = (uint32_t)(row * 272 + c * 16);
            size_t go = (size_t)(n0 + row) * KVW + kvh * DH + c * 8;
            cp_async16(sb + so,          ksh + go);
            cp_async16(sb + AT_ARR + so, vsh + go);
        }
    };

    const int n_tiles = (m0 + AT_BM) / AT_BN;   // >= 2 always

    prefetch(0, 0);
    cp_commit();
    prefetch(AT_BN, 1);
    cp_commit();

    // Q tile -> smem (plain stores), then hoist to registers
    for (int u = tid; u < AT_BM * 16; u += 256) {
        int row = u >> 4;
        int c   = u & 15;
        size_t go = (size_t)(m0 + row) * QW + h * DH + c * 8;
        uint32_t so = (uint32_t)(row * 272 + c * 16);
        *(uint4*)(asmem + AT_QOFF + so)         = *(const uint4*)(qsh + go);
        *(uint4*)(asmem + AT_QOFF + 34816 + so) = *(const uint4*)(qsl + go);
    }
    __syncthreads();

    uint32_t qfh[8][4], qfl[8][4];
#pragma unroll
    for (int ks = 0; ks < 8; ks++) {
        uint32_t qbase = (uint32_t)(w * 16 * 272 + ks * 32) + a_off;
        ldsm_x4(qfh[ks][0], qfh[ks][1], qfh[ks][2], qfh[ks][3], uQ + qbase);
        ldsm_x4(qfl[ks][0], qfl[ks][1], qfl[ks][2], qfl[ks][3], uQ + 34816 + qbase);
    }

    float m_[2] = { -CUDART_INF_F, -CUDART_INF_F };
    float l_[2] = { 0.f, 0.f };

    float accO[16][4];
#pragma unroll
    for (int a = 0; a < 16; a++)
#pragma unroll
        for (int c = 0; c < 4; c++) accO[a][c] = 0.f;

    const int row0 = m0 + w * 16 + gq;

    for (int tile = 0; tile < n_tiles; tile++) {
        const int n0 = tile * AT_BN;
        const int st = tile % 3;

        if (tile + 2 <= n_tiles) cp_wait<1>();
        else                     cp_wait<0>();
        __syncthreads();

        if (tile + 2 < n_tiles) {
            prefetch(n0 + 2 * AT_BN, (tile + 2) % 3);
            cp_commit();
        }

        const uint32_t kh = uS[st];
        const uint32_t sv = uS[st] + AT_ARR;

        // ---- S = Q @ K^T (fp16x2), warp tile 16x64 ----
        float accS[8][4];
#pragma unroll
        for (int bb = 0; bb < 8; bb++)
#pragma unroll
            for (int c = 0; c < 4; c++) accS[bb][c] = 0.f;

#pragma unroll
        for (int ks = 0; ks < 8; ks++) {
            const uint32_t kb = (uint32_t)(ks * 32);
#pragma unroll
            for (int ntp = 0; ntp < 4; ntp++) {
                uint32_t base = (uint32_t)(ntp * 16 * 272) + kb + b_off;
                uint32_t bh0, bh1, bh2, bh3;
                ldsm_x4(bh0, bh1, bh2, bh3, kh + base);
                mma16816h(accS[2 * ntp],     qfh[ks][0], qfh[ks][1], qfh[ks][2], qfh[ks][3], bh0, bh1);
                mma16816h(accS[2 * ntp],     qfl[ks][0], qfl[ks][1], qfl[ks][2], qfl[ks][3], bh0, bh1);
                mma16816h(accS[2 * ntp + 1], qfh[ks][0], qfh[ks][1], qfh[ks][2], qfh[ks][3], bh2, bh3);
                mma16816h(accS[2 * ntp + 1], qfl[ks][0], qfl[ks][1], qfl[ks][2], qfl[ks][3], bh2, bh3);
            }
        }

        // ---- causal mask ----
        if (n0 + AT_BN - 1 > m0) {
#pragma unroll
            for (int nt = 0; nt < 8; nt++) {
                int c0 = n0 + nt * 8 + 2 * tg;
                if (c0     > row0)     accS[nt][0] = -CUDART_INF_F;
                if (c0 + 1 > row0)     accS[nt][1] = -CUDART_INF_F;
                if (c0     > row0 + 8) accS[nt][2] = -CUDART_INF_F;
                if (c0 + 1 > row0 + 8) accS[nt][3] = -CUDART_INF_F;
            }
        }

        // ---- in-register online softmax ----
        float mx0 = accS[0][0], mx1 = accS[0][2];
#pragma unroll
        for (int nt = 0; nt < 8; nt++) {
            mx0 = fmaxf(mx0, fmaxf(accS[nt][0], accS[nt][1]));
            mx1 = fmaxf(mx1, fmaxf(accS[nt][2], accS[nt][3]));
        }
        mx0 = fmaxf(mx0, __shfl_xor_sync(0xffffffffu, mx0, 1));
        mx0 = fmaxf(mx0, __shfl_xor_sync(0xffffffffu, mx0, 2));
        mx1 = fmaxf(mx1, __shfl_xor_sync(0xffffffffu, mx1, 1));
        mx1 = fmaxf(mx1, __shfl_xor_sync(0xffffffffu, mx1, 2));

        float mn0 = fmaxf(m_[0], mx0);
        float mn1 = fmaxf(m_[1], mx1);
        float corr0 = __expf(m_[0] - mn0);
        float corr1 = __expf(m_[1] - mn1);
        float sum0 = 0.f, sum1 = 0.f;
#pragma unroll
        for (int nt = 0; nt < 8; nt++) {
            accS[nt][0] = __expf(accS[nt][0] - mn0);
            accS[nt][1] = __expf(accS[nt][1] - mn0);
            accS[nt][2] = __expf(accS[nt][2] - mn1);
            accS[nt][3] = __expf(accS[nt][3] - mn1);
            sum0 += accS[nt][0] + accS[nt][1];
            sum1 += accS[nt][2] + accS[nt][3];
        }
        sum0 += __shfl_xor_sync(0xffffffffu, sum0, 1);
        sum0 += __shfl_xor_sync(0xffffffffu, sum0, 2);
        sum1 += __shfl_xor_sync(0xffffffffu, sum1, 1);
        sum1 += __shfl_xor_sync(0xffffffffu, sum1, 2);
        l_[0] = l_[0] * corr0 + sum0;
        l_[1] = l_[1] * corr1 + sum1;
        m_[0] = mn0; m_[1] = mn1;

#pragma unroll
        for (int nt = 0; nt < 16; nt++) {
            accO[nt][0] *= corr0; accO[nt][1] *= corr0;
            accO[nt][2] *= corr1; accO[nt][3] *= corr1;
        }

        // ---- O += P @ V (fp16x2), warp tile 16x128, k=64 ----
#pragma unroll
        for (int kc = 0; kc < 4; kc++) {
            float p00 = accS[2 * kc][0],     p01 = accS[2 * kc][1];
            float p10 = accS[2 * kc][2],     p11 = accS[2 * kc][3];
            float p20 = accS[2 * kc + 1][0], p21 = accS[2 * kc + 1][1];
            float p30 = accS[2 * kc + 1][2], p31 = accS[2 * kc + 1][3];
            float h00 = __half2float(__float2half_rn(p00));
            float h01 = __half2float(__float2half_rn(p01));
            float h10 = __half2float(__float2half_rn(p10));
            float h11 = __half2float(__float2half_rn(p11));
            float h20 = __half2float(__float2half_rn(p20));
            float h21 = __half2float(__float2half_rn(p21));
            float h30 = __half2float(__float2half_rn(p30));
            float h31 = __half2float(__float2half_rn(p31));
            uint32_t ph0 = pack_h2(h00, h01);
            uint32_t ph1 = pack_h2(h10, h11);
            uint32_t ph2 = pack_h2(h20, h21);
            uint32_t ph3 = pack_h2(h30, h31);
            uint32_t pl0 = pack_h2(p00 - h00, p01 - h01);
            uint32_t pl1 = pack_h2(p10 - h10, p11 - h11);
            uint32_t pl2 = pack_h2(p20 - h20, p21 - h21);
            uint32_t pl3 = pack_h2(p30 - h30, p31 - h31);

#pragma unroll
            for (int ncg = 0; ncg < 8; ncg++) {
                uint32_t base_off = (uint32_t)(kc * 16 * 272 + ncg * 32) + vlane_off;
                uint32_t v0, v1, v2, v3;
                ldsm_x4_t(v0, v1, v2, v3, sv + base_off);
                mma16816h(accO[ncg * 2],     ph0, ph1, ph2, ph3, v0, v1);
                mma16816h(accO[ncg * 2],     pl0, pl1, pl2, pl3, v0, v1);
                mma16816h(accO[ncg * 2 + 1], ph0, ph1, ph2, ph3, v2, v3);
                mma16816h(accO[ncg * 2 + 1], pl0, pl1, pl2, pl3, v2, v3);
            }
        }
    }

    // ---- normalize + single-fp16 write ----
    float i0 = 1.f / l_[0];
    float i1 = 1.f / l_[1];
#pragma unroll
    for (int nt = 0; nt < 16; nt++) {
        int col = h * DH + nt * 8 + 2 * tg;
        size_t o0 = (size_t)row0 * HID + col;
        size_t o1 = (size_t)(row0 + 8) * HID + col;
        *(uint32_t*)(oh + o0) = pack_h2(accO[nt][0] * i0, accO[nt][1] * i0);
        *(uint32_t*)(oh + o1) = pack_h2(accO[nt][2] * i1, accO[nt][3] * i1);
    }
}

// ---------------------------------------------------------------------------
// Launch
// ---------------------------------------------------------------------------
extern "C" void kernel_launch(void* const* d_in, const int* in_sizes, int n_in,
                              void* d_out, int out_size)
{
    const int*   positions = (const int*)d_in[0];
    const float* hidden    = (const float*)d_in[1];
    const float* w_qkv     = (const float*)d_in[2];
    const float* w_o       = (const float*)d_in[3];
    const float* q_norm_w  = (const float*)d_in[4];
    const float* k_norm_w  = (const float*)d_in[5];
    float*       out       = (float*)d_out;

    __half *ah, *bh, *qsh, *qsl, *ksh, *vsh;
    float2* rope;
    cudaGetSymbolAddress((void**)&ah, g_ah);
    cudaGetSymbolAddress((void**)&bh, g_bh);
    cudaGetSymbolAddress((void**)&qsh, g_qsh);
    cudaGetSymbolAddress((void**)&qsl, g_qsl);
    cudaGetSymbolAddress((void**)&ksh, g_ksh);
    cudaGetSymbolAddress((void**)&vsh, g_vsh);
    cudaGetSymbolAddress((void**)&rope, g_rope);

    cudaFuncSetAttribute(gemm_mma_kernel_t<true>,
                         cudaFuncAttributeMaxDynamicSharedMemorySize, GEMM_SMEM);
    cudaFuncSetAttribute(gemm_mma_kernel_t<false>,
                         cudaFuncAttributeMaxDynamicSharedMemorySize, GEMM_SMEM);
    static_assert(ATTN_SMEM <= 227 * 1024, "attn smem over limit");
    cudaFuncSetAttribute(attn_kernel,
                         cudaFuncAttributeMaxDynamicSharedMemorySize, ATTN_SMEM);

    // 1. Convert hidden to fp16 (+ RoPE table); transpose w_qkv to fp16.
    {
        int n = TT * HID;
        convert_kernel<<<n / 4 / 256, 256>>>(hidden, ah, n, positions, rope);
        dim3 tg(QKVW / 32, HID / 32);
        transpose_half_kernel<<<tg, dim3(32, 8)>>>(w_qkv, bh, HID, QKVW);
    }

    // 2. QKV projection (single fp16) with FUSED norm/rope/split epilogue.
    {
        dim3 grid(QKVW / 128, TT / 128);
        gemm_mma_kernel_t<true><<<grid, 256, GEMM_SMEM>>>(
            TT, QKVW, HID, ah, bh,
            nullptr, rope, q_norm_w, k_norm_w,
            qsh, qsl, ksh, vsh);
    }

    // 3. Causal GQA flash attention (fp16x2); writes single fp16 into ah.
    {
        dim3 grid(NH, TT / AT_BM);
        attn_kernel<<<grid, 256, ATTN_SMEM>>>(
            qsh, qsl, ksh, vsh, ah);
    }

    // 4. transpose w_o to fp16 (bh free after QKV GEMM).
    {
        dim3 tg(HID / 32, (NH * DH) / 32);
        transpose_half_kernel<<<tg, dim3(32, 8)>>>(w_o, bh, NH * DH, HID);
    }

    // 5. Output projection (single fp16, plain fp32 epilogue).
    {
        dim3 grid(HID / 128, TT / 128);
        gemm_mma_kernel_t<false><<<grid, 256, GEMM_SMEM>>>(
            TT, HID, NH * DH, ah, bh,
            out, nullptr, nullptr, nullptr,
            nullptr, nullptr, nullptr, nullptr);
    }
}